// round 10
// baseline (speedup 1.0000x reference)
#include <cuda_runtime.h>
#include <cuda_bf16.h>
#include <cstdint>

// ---------------- problem constants ----------------
#define DEPTH  4
#define HEADS  8
#define DHEAD  64
#define DIM    512
#define MLPD   2048
#define RED    128
#define BB     8
#define PP     4
#define NN     256
#define TT     (BB*PP*NN)     // 8192 tokens

// ---------------- scratch ----------------
static const size_t OFF_X   = 0;                               // f32 residual
static const size_t OFF_Y   = OFF_X   + (size_t)TT*DIM;        // bf16 LN out
static const size_t OFF_QKV = OFF_Y   + (size_t)TT*DIM;        // f32
static const size_t OFF_ATT = OFF_QKV + (size_t)TT*3*DIM;      // bf16
static const size_t OFF_H1  = OFF_ATT + (size_t)TT*DIM;        // bf16
static const size_t OFF_H   = OFF_H1  + (size_t)TT*MLPD;       // f32
static const size_t OFF_BX  = OFF_H   + (size_t)TT*DIM;        // bf16
static const size_t OFF_XG  = OFF_BX  + (size_t)TT*DIM;        // bf16
static const size_t OFF_XGA = OFF_XG  + (size_t)BB*NN*DIM;     // bf16
static const size_t OFF_XL  = OFF_XGA + (size_t)BB*NN*RED;     // bf16
static const size_t OFF_CA  = OFF_XL  + (size_t)TT*RED;        // f32
static const size_t OFF_SA  = OFF_CA  + (size_t)BB*NN*DIM;     // f32
static const size_t OFF_WT  = OFF_SA  + TT;                    // transposed bf16 weights

// transposed-weight sub-offsets (bf16 element units): layout [d][n][k]
static const size_t WT_QKV = 0;                                   // 4*1536*512
static const size_t WT_O   = WT_QKV + (size_t)4*1536*512;
static const size_t WT_W1  = WT_O   + (size_t)4*512*512;
static const size_t WT_W2  = WT_W1  + (size_t)4*2048*512;
static const size_t WT_WG  = WT_W2  + (size_t)4*512*2048;
static const size_t WT_WL  = WT_WG  + (size_t)4*128*512;
static const size_t WT_WC  = WT_WL  + (size_t)4*128*512;
static const size_t WT_TOT = WT_WC  + (size_t)4*512*128;

static const size_t SCRATCH_FLOATS = OFF_WT + (WT_TOT + 1) / 2;

__device__ float g_scratch[SCRATCH_FLOATS];

// ---------------- small helpers ----------------
__global__ void copy_k(const float* __restrict__ a, float* __restrict__ b, int n) {
    int i = blockIdx.x * blockDim.x + threadIdx.x;
    if (i < n) b[i] = a[i];
}

__device__ __forceinline__ uint32_t smem_u32(const void* p) {
    uint32_t a;
    asm("{ .reg .u64 t; cvta.to.shared.u64 t, %1; cvt.u32.u64 %0, t; }" : "=r"(a) : "l"(p));
    return a;
}
__device__ __forceinline__ void cp16(uint32_t dst, const void* src) {
    asm volatile("cp.async.cg.shared.global [%0], [%1], 16;\n" :: "r"(dst), "l"(src));
}
__device__ __forceinline__ void cp_commit() {
    asm volatile("cp.async.commit_group;\n");
}
template<int N>
__device__ __forceinline__ void cp_wait() {
    asm volatile("cp.async.wait_group %0;\n" :: "n"(N));
}

// tiled transpose-pack: W[d][K][N] f32 -> Wt[d][N][K] bf16
__global__ void packwt_k(const float* __restrict__ W, __nv_bfloat16* __restrict__ Wt,
                         int K, int N)
{
    __shared__ float t[32][33];
    int k0 = blockIdx.x * 32, n0 = blockIdx.y * 32, d = blockIdx.z;
    const float* Wd = W + (size_t)d * K * N;
    #pragma unroll
    for (int i = 0; i < 32; i += 8)
        t[threadIdx.y + i][threadIdx.x] =
            Wd[(size_t)(k0 + threadIdx.y + i) * N + n0 + threadIdx.x];
    __syncthreads();
    __nv_bfloat16* out = Wt + (size_t)d * N * K;
    #pragma unroll
    for (int i = 0; i < 32; i += 8)
        out[(size_t)(n0 + threadIdx.y + i) * K + k0 + threadIdx.x] =
            __float2bfloat16(t[threadIdx.x][threadIdx.y + i]);
}

// ---------------- layernorm: fp32 in, bf16 out ----------------
__global__ __launch_bounds__(128)
void ln_k(const float* __restrict__ in, __nv_bfloat16* __restrict__ out,
          const float* __restrict__ g, const float* __restrict__ b)
{
    int t = blockIdx.x;
    int lane = threadIdx.x & 31, w = threadIdx.x >> 5;
    float4 v = ((const float4*)(in + (size_t)t*DIM))[threadIdx.x];
    float s = v.x + v.y + v.z + v.w;
    float q = v.x*v.x + v.y*v.y + v.z*v.z + v.w*v.w;
    #pragma unroll
    for (int o = 16; o; o >>= 1) {
        s += __shfl_xor_sync(0xffffffffu, s, o);
        q += __shfl_xor_sync(0xffffffffu, q, o);
    }
    __shared__ float ss[4], qq[4];
    if (lane == 0) { ss[w] = s; qq[w] = q; }
    __syncthreads();
    s = ss[0] + ss[1] + ss[2] + ss[3];
    q = qq[0] + qq[1] + qq[2] + qq[3];
    float mean = s * (1.0f / DIM);
    float var  = q * (1.0f / DIM) - mean * mean;
    float inv  = rsqrtf(var + 1e-5f);
    float4 gg = ((const float4*)g)[threadIdx.x];
    float4 bb = ((const float4*)b)[threadIdx.x];
    float o0 = (v.x - mean) * inv * gg.x + bb.x;
    float o1 = (v.y - mean) * inv * gg.y + bb.y;
    float o2 = (v.z - mean) * inv * gg.z + bb.z;
    float o3 = (v.w - mean) * inv * gg.w + bb.w;
    __nv_bfloat162* op = (__nv_bfloat162*)(out + (size_t)t*DIM) + 2*threadIdx.x;
    op[0] = __floats2bfloat162_rn(o0, o1);
    op[1] = __floats2bfloat162_rn(o2, o3);
}

// ---------------- bf16 tensor-core GEMM (ldmatrix + cp.async) -------------
// C[M,N] = A[M,K] @ Bt[N,K]^T (+ epilogue). A bf16 row-major, Bt bf16 [N][K].
// BM=BN=128, BK=32, 3-stage cp.async pipeline, 8 warps 2x4, warp tile 64x32.
// Tile smem layout (per 128x32 bf16 tile, 8192B): row r (0..127), 16B chunk c (0..3):
//   off(r,c) = (r>>1)*128 + (((4*(r&1)+c) ^ ((r>>1)&7)) * 16)
// k16 sub-step (c -> c+2) toggles bit1 of the pre-swizzle chunk index, which on
// the swizzled byte address is addr ^ 32 (NOT addr + 32).
#define EPI_NONE 0
#define EPI_BIAS 1
#define EPI_GELU 2
#define EPI_SIG  3
#define EPI_RES  4

#define GSTAGES 3
#define TILEB   8192
#define STAGEB  (2*TILEB)

__device__ __forceinline__ uint32_t tile_off(int r, int c) {
    return (uint32_t)((r >> 1) * 128 + (((4 * (r & 1) + c) ^ ((r >> 1) & 7)) * 16));
}

template<int EPI, int OBF>
__global__ __launch_bounds__(256, 2)
void bgemm_k(const __nv_bfloat16* __restrict__ Abf, const __nv_bfloat16* __restrict__ Bt,
             void* __restrict__ Cout, int M, int N, int K,
             const float* __restrict__ bias, const float* __restrict__ res)
{
    __shared__ __align__(1024) uint8_t smem[GSTAGES * STAGEB];
    const uint32_t sbase = smem_u32(smem);

    const int tid   = threadIdx.x;
    const int warp  = tid >> 5, lane = tid & 31;
    const int group = lane >> 2, tig = lane & 3;
    const int wm = (warp >> 2) * 64;
    const int wn = (warp & 3) * 32;
    const int m0 = blockIdx.y * 128, n0 = blockIdx.x * 128;

    // cp.async mapping: thread t handles 2 chunks of A and 2 of B per stage
    auto stage_load = [&](int kt, int s) {
        #pragma unroll
        for (int i = 0; i < 2; i++) {
            int idx = i * 256 + tid;
            int r = idx >> 2, c = idx & 3;
            uint32_t o = tile_off(r, c);
            const char* ga = (const char*)Abf + ((size_t)(m0 + r) * K + kt * 32 + c * 8) * 2;
            cp16(sbase + s * STAGEB + o, ga);
            const char* gb = (const char*)Bt + ((size_t)(n0 + r) * K + kt * 32 + c * 8) * 2;
            cp16(sbase + s * STAGEB + TILEB + o, gb);
        }
        cp_commit();
    };

    // ldmatrix per-lane base addresses (k16=0, mi=0 / p=0)
    const int rA = wm + (lane & 7) + ((lane >> 3) & 1) * 8;
    const int cA = (lane >> 4) & 1;
    const uint32_t aBase = sbase + tile_off(rA, cA);
    const int rB = wn + (lane & 7) + ((lane >> 4) & 1) * 8;
    const int cB = (lane >> 3) & 1;
    const uint32_t bBase = sbase + TILEB + tile_off(rB, cB);

    const int nk = K / 32;

    stage_load(0, 0);
    stage_load(1 < nk ? 1 : 0, 1);
    cp_wait<1>();
    __syncthreads();

    float acc[4][4][4];
    #pragma unroll
    for (int mi = 0; mi < 4; mi++)
        #pragma unroll
        for (int ni = 0; ni < 4; ni++)
            #pragma unroll
            for (int r = 0; r < 4; r++) acc[mi][ni][r] = 0.f;

    for (int kt = 0; kt < nk; kt++) {
        const int buf = kt % GSTAGES;
        const uint32_t abuf = aBase + buf * STAGEB;
        const uint32_t bbuf = bBase + buf * STAGEB;

        if (kt + GSTAGES - 1 < nk) {
            stage_load(kt + GSTAGES - 1, (kt + GSTAGES - 1) % GSTAGES);
        } else {
            cp_commit();   // keep group accounting uniform
        }

        #pragma unroll
        for (int k16 = 0; k16 < 2; k16++) {
            const uint32_t koff = k16 ? 32u : 0u;   // applied via XOR (swizzle-aware)
            uint32_t a[4][4], b[4][2];
            #pragma unroll
            for (int mi = 0; mi < 4; mi++) {
                asm volatile(
                    "ldmatrix.sync.aligned.m8n8.x4.shared.b16 {%0,%1,%2,%3}, [%4];"
                    : "=r"(a[mi][0]), "=r"(a[mi][1]), "=r"(a[mi][2]), "=r"(a[mi][3])
                    : "r"((abuf + mi * 1024u) ^ koff));
            }
            #pragma unroll
            for (int p = 0; p < 2; p++) {
                asm volatile(
                    "ldmatrix.sync.aligned.m8n8.x4.shared.b16 {%0,%1,%2,%3}, [%4];"
                    : "=r"(b[2*p][0]), "=r"(b[2*p][1]), "=r"(b[2*p+1][0]), "=r"(b[2*p+1][1])
                    : "r"((bbuf + p * 1024u) ^ koff));
            }
            #pragma unroll
            for (int mi = 0; mi < 4; mi++)
                #pragma unroll
                for (int ni = 0; ni < 4; ni++) {
                    asm volatile(
                        "mma.sync.aligned.m16n8k16.row.col.f32.bf16.bf16.f32 "
                        "{%0,%1,%2,%3}, {%4,%5,%6,%7}, {%8,%9}, {%0,%1,%2,%3};"
                        : "+f"(acc[mi][ni][0]), "+f"(acc[mi][ni][1]),
                          "+f"(acc[mi][ni][2]), "+f"(acc[mi][ni][3])
                        : "r"(a[mi][0]), "r"(a[mi][1]), "r"(a[mi][2]), "r"(a[mi][3]),
                          "r"(b[ni][0]), "r"(b[ni][1]));
                }
        }

        cp_wait<1>();        // next-stage buffer complete
        __syncthreads();     // all warps done reading buf before it is overwritten
    }

    // epilogue
    #pragma unroll
    for (int mi = 0; mi < 4; mi++) {
        #pragma unroll
        for (int half = 0; half < 2; half++) {
            int m = m0 + wm + mi * 16 + group + half * 8;
            #pragma unroll
            for (int ni = 0; ni < 4; ni++) {
                int n = n0 + wn + ni * 8 + tig * 2;
                float v0 = acc[mi][ni][half * 2 + 0];
                float v1 = acc[mi][ni][half * 2 + 1];
                if (EPI != EPI_NONE) { v0 += bias[n]; v1 += bias[n + 1]; }
                if (EPI == EPI_GELU) {
                    v0 = 0.5f * v0 * (1.0f + erff(v0 * 0.70710678118654752f));
                    v1 = 0.5f * v1 * (1.0f + erff(v1 * 0.70710678118654752f));
                } else if (EPI == EPI_SIG) {
                    v0 = 1.0f / (1.0f + __expf(-v0));
                    v1 = 1.0f / (1.0f + __expf(-v1));
                } else if (EPI == EPI_RES) {
                    v0 += res[(size_t)m * N + n];
                    v1 += res[(size_t)m * N + n + 1];
                }
                if (OBF) {
                    __nv_bfloat162 h2 = __floats2bfloat162_rn(v0, v1);
                    *(__nv_bfloat162*)((__nv_bfloat16*)Cout + (size_t)m * N + n) = h2;
                } else {
                    *(float2*)((float*)Cout + (size_t)m * N + n) = make_float2(v0, v1);
                }
            }
        }
    }
}

// ---------------- attention: 1 block per (b,p,h), 256 threads -------------
__global__ __launch_bounds__(256)
void attn_k(const float* __restrict__ qkv, __nv_bfloat16* __restrict__ out)
{
    extern __shared__ float sm[];
    float* Ks = sm;
    float* Vs = sm + NN * DHEAD;
    int bid = blockIdx.x;
    int h  = bid & 7;
    int bp = bid >> 3;
    int tbase = bp * NN;
    int hoff = h * DHEAD;

    for (int idx = threadIdx.x; idx < NN * DHEAD; idx += 256) {
        int r = idx >> 6, c = idx & 63;
        size_t g = (size_t)(tbase + r) * (3 * DIM);
        Ks[idx] = qkv[g + DIM     + hoff + c];
        Vs[idx] = qkv[g + 2 * DIM + hoff + c];
    }
    __syncthreads();

    int t = tbase + threadIdx.x;
    float q[64];
    {
        const float4* qp = (const float4*)(qkv + (size_t)t * (3 * DIM) + hoff);
        #pragma unroll
        for (int i = 0; i < 16; i++) {
            float4 v = qp[i];
            q[4*i] = v.x; q[4*i+1] = v.y; q[4*i+2] = v.z; q[4*i+3] = v.w;
        }
    }
    const float scale = 0.125f;

    float m = -1e30f;
    for (int j = 0; j < NN; j++) {
        const float4* kp = (const float4*)(Ks + j * 64);
        float s = 0.f;
        #pragma unroll
        for (int i = 0; i < 16; i++) {
            float4 kv = kp[i];
            s += q[4*i]*kv.x + q[4*i+1]*kv.y + q[4*i+2]*kv.z + q[4*i+3]*kv.w;
        }
        m = fmaxf(m, s * scale);
    }

    float o[64];
    #pragma unroll
    for (int i = 0; i < 64; i++) o[i] = 0.f;
    float l = 0.f;
    for (int j = 0; j < NN; j++) {
        const float4* kp = (const float4*)(Ks + j * 64);
        float s = 0.f;
        #pragma unroll
        for (int i = 0; i < 16; i++) {
            float4 kv = kp[i];
            s += q[4*i]*kv.x + q[4*i+1]*kv.y + q[4*i+2]*kv.z + q[4*i+3]*kv.w;
        }
        float p = __expf(s * scale - m);
        l += p;
        const float4* vp = (const float4*)(Vs + j * 64);
        #pragma unroll
        for (int i = 0; i < 16; i++) {
            float4 vv = vp[i];
            o[4*i]   += p * vv.x;
            o[4*i+1] += p * vv.y;
            o[4*i+2] += p * vv.z;
            o[4*i+3] += p * vv.w;
        }
    }
    float inv = 1.0f / l;
    __nv_bfloat162* op = (__nv_bfloat162*)(out + (size_t)t * DIM + hoff);
    #pragma unroll
    for (int i = 0; i < 16; i++) {
        op[2*i]   = __floats2bfloat162_rn(o[4*i]   * inv, o[4*i+1] * inv);
        op[2*i+1] = __floats2bfloat162_rn(o[4*i+2] * inv, o[4*i+3] * inv);
    }
}

// ---------------- biattn pieces ----------------
__global__ void mean_k(const __nv_bfloat16* __restrict__ bx, __nv_bfloat16* __restrict__ xg)
{
    int idx = blockIdx.x * blockDim.x + threadIdx.x;
    if (idx >= BB * NN * DIM) return;
    int d = idx % DIM;
    int n = (idx / DIM) % NN;
    int b = idx / (DIM * NN);
    size_t base = ((size_t)(b * PP) * NN + n) * DIM + d;
    const size_t st = (size_t)NN * DIM;
    float s = __bfloat162float(bx[base]) + __bfloat162float(bx[base + st])
            + __bfloat162float(bx[base + 2*st]) + __bfloat162float(bx[base + 3*st]);
    xg[idx] = __float2bfloat16(0.25f * s);
}

__global__ __launch_bounds__(256)
void sattn_k(const __nv_bfloat16* __restrict__ xl, const __nv_bfloat16* __restrict__ xga,
             const float* __restrict__ ws, const float* __restrict__ bsc,
             float* __restrict__ sa)
{
    int gtid = blockIdx.x * 256 + threadIdx.x;
    int t = gtid >> 5;
    int lane = threadIdx.x & 31;
    if (t >= TT) return;
    int b = t / (PP * NN);
    int n = t % NN;
    const __nv_bfloat16* xlp = xl  + (size_t)t * RED;
    const __nv_bfloat16* xgp = xga + ((size_t)b * NN + n) * RED;
    float s = 0.f;
    for (int i = lane; i < RED; i += 32)
        s += __bfloat162float(xlp[i]) * ws[i] + __bfloat162float(xgp[i]) * ws[RED + i];
    #pragma unroll
    for (int o = 16; o; o >>= 1) s += __shfl_xor_sync(0xffffffffu, s, o);
    if (lane == 0) sa[t] = 1.0f / (1.0f + __expf(-(s + bsc[0])));
}

__global__ void fuse_k(const float* __restrict__ h, const float* __restrict__ ca,
                       const float* __restrict__ sa, float* __restrict__ x)
{
    int idx = blockIdx.x * blockDim.x + threadIdx.x;
    if (idx >= TT * DIM) return;
    int t = idx / DIM;
    int d = idx % DIM;
    int b = t / (PP * NN);
    int n = t % NN;
    x[idx] += h[idx] * ca[((size_t)b * NN + n) * DIM + d] * sa[t];
}

// ---------------- host driver ----------------
extern "C" void kernel_launch(void* const* d_in, const int* in_sizes, int n_in,
                              void* d_out, int out_size)
{
    const float* x_in  = (const float*)d_in[0];
    const float* ln1_g = (const float*)d_in[1];
    const float* ln1_b = (const float*)d_in[2];
    const float* w_qkv = (const float*)d_in[3];
    const float* w_o   = (const float*)d_in[4];
    const float* b_o   = (const float*)d_in[5];
    const float* ln2_g = (const float*)d_in[6];
    const float* ln2_b = (const float*)d_in[7];
    const float* w1    = (const float*)d_in[8];
    const float* b1    = (const float*)d_in[9];
    const float* w2    = (const float*)d_in[10];
    const float* b2    = (const float*)d_in[11];
    const float* bn_g  = (const float*)d_in[12];
    const float* bn_b  = (const float*)d_in[13];
    const float* wg    = (const float*)d_in[14];
    const float* bg    = (const float*)d_in[15];
    const float* wl    = (const float*)d_in[16];
    const float* bl    = (const float*)d_in[17];
    const float* wc    = (const float*)d_in[18];
    const float* bc    = (const float*)d_in[19];
    const float* ws    = (const float*)d_in[20];
    const float* bs    = (const float*)d_in[21];

    float* base = nullptr;
    cudaGetSymbolAddress((void**)&base, g_scratch);
    float*          X   = base + OFF_X;
    __nv_bfloat16*  Y   = (__nv_bfloat16*)(base + OFF_Y);
    float*          QKV = base + OFF_QKV;
    __nv_bfloat16*  ATT = (__nv_bfloat16*)(base + OFF_ATT);
    __nv_bfloat16*  H1  = (__nv_bfloat16*)(base + OFF_H1);
    float*          H   = base + OFF_H;
    __nv_bfloat16*  BX  = (__nv_bfloat16*)(base + OFF_BX);
    __nv_bfloat16*  XG  = (__nv_bfloat16*)(base + OFF_XG);
    __nv_bfloat16*  XGA = (__nv_bfloat16*)(base + OFF_XGA);
    __nv_bfloat16*  XL  = (__nv_bfloat16*)(base + OFF_XL);
    float*          CA  = base + OFF_CA;
    float*          SA  = base + OFF_SA;
    __nv_bfloat16*  WT  = (__nv_bfloat16*)(base + OFF_WT);

    const int ATTN_SMEM = 2 * NN * DHEAD * sizeof(float);   // 128 KB
    cudaFuncSetAttribute((const void*)attn_k,
                         cudaFuncAttributeMaxDynamicSharedMemorySize, ATTN_SMEM);

    const int EW = 256;
    dim3 tp(32, 8);

    // transpose-pack all weights to [d][n][k] bf16 (once per launch)
    packwt_k<<<dim3(512/32, 1536/32, 4), tp>>>(w_qkv, WT + WT_QKV, 512, 1536);
    packwt_k<<<dim3(512/32,  512/32, 4), tp>>>(w_o,   WT + WT_O,   512,  512);
    packwt_k<<<dim3(512/32, 2048/32, 4), tp>>>(w1,    WT + WT_W1,  512, 2048);
    packwt_k<<<dim3(2048/32, 512/32, 4), tp>>>(w2,    WT + WT_W2, 2048,  512);
    packwt_k<<<dim3(512/32,  128/32, 4), tp>>>(wg,    WT + WT_WG,  512,  128);
    packwt_k<<<dim3(512/32,  128/32, 4), tp>>>(wl,    WT + WT_WL,  512,  128);
    packwt_k<<<dim3(128/32,  512/32, 4), tp>>>(wc,    WT + WT_WC,  128,  512);

    copy_k<<<(TT*DIM + EW - 1) / EW, EW>>>(x_in, X, TT * DIM);

    for (int l = 0; l < DEPTH; l++) {
        // ---- attention half ----
        ln_k<<<TT, 128>>>(X, Y, ln1_g + l*DIM, ln1_b + l*DIM);
        bgemm_k<EPI_NONE,0><<<dim3(3*DIM/128, TT/128), 256>>>(
            Y, WT + WT_QKV + (size_t)l*1536*512, QKV, TT, 3*DIM, DIM, nullptr, nullptr);
        attn_k<<<BB*PP*HEADS, 256, ATTN_SMEM>>>(QKV, ATT);
        bgemm_k<EPI_RES,0><<<dim3(DIM/128, TT/128), 256>>>(
            ATT, WT + WT_O + (size_t)l*512*512, X, TT, DIM, DIM, b_o + l*DIM, X);

        // ---- mlp half ----
        ln_k<<<TT, 128>>>(X, Y, ln2_g + l*DIM, ln2_b + l*DIM);
        bgemm_k<EPI_GELU,1><<<dim3(MLPD/128, TT/128), 256>>>(
            Y, WT + WT_W1 + (size_t)l*2048*512, H1, TT, MLPD, DIM, b1 + l*MLPD, nullptr);
        bgemm_k<EPI_BIAS,0><<<dim3(DIM/128, TT/128), 256>>>(
            H1, WT + WT_W2 + (size_t)l*512*2048, H, TT, DIM, MLPD, b2 + l*DIM, nullptr);

        // ---- biattn ----
        ln_k<<<TT, 128>>>(H, BX, bn_g + l*DIM, bn_b + l*DIM);
        mean_k<<<(BB*NN*DIM + EW - 1) / EW, EW>>>(BX, XG);
        bgemm_k<EPI_GELU,1><<<dim3(RED/128, BB*NN/128), 256>>>(
            XG, WT + WT_WG + (size_t)l*128*512, XGA, BB*NN, RED, DIM, bg + l*RED, nullptr);
        bgemm_k<EPI_GELU,1><<<dim3(RED/128, TT/128), 256>>>(
            BX, WT + WT_WL + (size_t)l*128*512, XL, TT, RED, DIM, bl + l*RED, nullptr);
        bgemm_k<EPI_SIG,0><<<dim3(DIM/128, BB*NN/128), 256>>>(
            XGA, WT + WT_WC + (size_t)l*512*128, CA, BB*NN, DIM, RED, bc + l*DIM, nullptr);
        sattn_k<<<(TT*32 + 255) / 256, 256>>>(XL, XGA, ws + l*2*RED, bs + l, SA);
        fuse_k<<<(TT*DIM + EW - 1) / EW, EW>>>(H, CA, SA, X);
    }

    copy_k<<<(TT*DIM + EW - 1) / EW, EW>>>(X, (float*)d_out, TT * DIM);
}

// round 13
// speedup vs baseline: 1.4156x; 1.4156x over previous
#include <cuda_runtime.h>
#include <cuda_bf16.h>
#include <cstdint>

// ---------------- problem constants ----------------
#define DEPTH  4
#define HEADS  8
#define DHEAD  64
#define DIM    512
#define MLPD   2048
#define RED    128
#define BB     8
#define PP     4
#define NN     256
#define TT     (BB*PP*NN)     // 8192 tokens

// ---------------- scratch ----------------
static const size_t OFF_X   = 0;                               // f32 residual
static const size_t OFF_Y   = OFF_X   + (size_t)TT*DIM;        // bf16 LN out
static const size_t OFF_QKV = OFF_Y   + (size_t)TT*DIM;        // f32
static const size_t OFF_ATT = OFF_QKV + (size_t)TT*3*DIM;      // bf16
static const size_t OFF_H1  = OFF_ATT + (size_t)TT*DIM;        // bf16
static const size_t OFF_H   = OFF_H1  + (size_t)TT*MLPD;       // f32
static const size_t OFF_BX  = OFF_H   + (size_t)TT*DIM;        // bf16
static const size_t OFF_XG  = OFF_BX  + (size_t)TT*DIM;        // bf16
static const size_t OFF_XGA = OFF_XG  + (size_t)BB*NN*DIM;     // bf16
static const size_t OFF_XL  = OFF_XGA + (size_t)BB*NN*RED;     // bf16
static const size_t OFF_CA  = OFF_XL  + (size_t)TT*RED;        // f32
static const size_t OFF_SA  = OFF_CA  + (size_t)BB*NN*DIM;     // f32
static const size_t OFF_WP  = OFF_SA  + TT;                    // packed bf16x2 weights (uint32)

// packed-weight sub-offsets (uint32 units)
static const size_t WP_QKV = 0;                                   // 4*256*1536
static const size_t WP_O   = WP_QKV + (size_t)4*256*1536;         // 4*256*512
static const size_t WP_W1  = WP_O   + (size_t)4*256*512;          // 4*256*2048
static const size_t WP_W2  = WP_W1  + (size_t)4*256*2048;         // 4*1024*512
static const size_t WP_WG  = WP_W2  + (size_t)4*1024*512;         // 4*256*128
static const size_t WP_WL  = WP_WG  + (size_t)4*256*128;          // 4*256*128
static const size_t WP_WC  = WP_WL  + (size_t)4*256*128;          // 4*64*512
static const size_t WP_TOT = WP_WC  + (size_t)4*64*512;

static const size_t SCRATCH_FLOATS = OFF_WP + WP_TOT;

__device__ float g_scratch[SCRATCH_FLOATS];

// ---------------- helpers ----------------
__global__ void copy_k(const float* __restrict__ a, float* __restrict__ b, int n) {
    int i = blockIdx.x * blockDim.x + threadIdx.x;
    if (i < n) b[i] = a[i];
}

// pack fp32 weights [D][K][N] -> bf16x2 pairs along K: Wp[(d*(K/2)+p)*N + n]
__global__ void packw_k(const float* __restrict__ W, uint32_t* __restrict__ Wp,
                        int K, int N, int total)
{
    int idx = blockIdx.x * blockDim.x + threadIdx.x;
    if (idx >= total) return;
    int n  = idx % N;
    int rp = idx / N;
    int p  = rp % (K >> 1);
    int d  = rp / (K >> 1);
    const float* s = W + ((size_t)d * K + 2 * p) * N + n;
    __nv_bfloat162 h = __floats2bfloat162_rn(s[0], s[N]);
    ((__nv_bfloat162*)Wp)[idx] = h;
}

// ---------------- layernorm: fp32 in, bf16 out ----------------
__global__ __launch_bounds__(128)
void ln_k(const float* __restrict__ in, __nv_bfloat16* __restrict__ out,
          const float* __restrict__ g, const float* __restrict__ b)
{
    int t = blockIdx.x;
    int lane = threadIdx.x & 31, w = threadIdx.x >> 5;
    float4 v = ((const float4*)(in + (size_t)t*DIM))[threadIdx.x];
    float s = v.x + v.y + v.z + v.w;
    float q = v.x*v.x + v.y*v.y + v.z*v.z + v.w*v.w;
    #pragma unroll
    for (int o = 16; o; o >>= 1) {
        s += __shfl_xor_sync(0xffffffffu, s, o);
        q += __shfl_xor_sync(0xffffffffu, q, o);
    }
    __shared__ float ss[4], qq[4];
    if (lane == 0) { ss[w] = s; qq[w] = q; }
    __syncthreads();
    s = ss[0] + ss[1] + ss[2] + ss[3];
    q = qq[0] + qq[1] + qq[2] + qq[3];
    float mean = s * (1.0f / DIM);
    float var  = q * (1.0f / DIM) - mean * mean;
    float inv  = rsqrtf(var + 1e-5f);
    float4 gg = ((const float4*)g)[threadIdx.x];
    float4 bb = ((const float4*)b)[threadIdx.x];
    float o0 = (v.x - mean) * inv * gg.x + bb.x;
    float o1 = (v.y - mean) * inv * gg.y + bb.y;
    float o2 = (v.z - mean) * inv * gg.z + bb.z;
    float o3 = (v.w - mean) * inv * gg.w + bb.w;
    __nv_bfloat162* op = (__nv_bfloat162*)(out + (size_t)t*DIM) + 2*threadIdx.x;
    op[0] = __floats2bfloat162_rn(o0, o1);
    op[1] = __floats2bfloat162_rn(o2, o3);
}

// ---------------- bf16 tensor-core GEMM -----------------------------------
// C[M,N] = A[M,K] @ B[K,N] (+ epilogue).
// A: bf16 row-major (loaded as k-pair uint32). B: pre-packed bf16x2 pairs [K/2][N].
// BM=BN=128, BK=32, 256 threads, 8 warps 2x4, warp tile 64x32, mma m16n8k16.
// Requires M%128==0, N%128==0, K%32==0.
#define EPI_NONE 0
#define EPI_BIAS 1
#define EPI_GELU 2
#define EPI_SIG  3
#define EPI_RES  4

#define ASTR 20    // A smem row stride (uint32): banks 20*group+tig all-distinct
#define BSTR 136   // B smem row stride (uint32): banks 8*tig+group all-distinct

template<int EPI, int OBF>
__global__ __launch_bounds__(256, 2)
void bgemm_k(const __nv_bfloat16* __restrict__ Abf, const uint32_t* __restrict__ Bp,
             void* __restrict__ Cout, int M, int N, int K,
             const float* __restrict__ bias, const float* __restrict__ res)
{
    __shared__ uint32_t As[2][128][ASTR];   // [row][k-pair]
    __shared__ uint32_t Bs[2][16][BSTR];    // [k-pair][n]

    const uint32_t* A32 = (const uint32_t*)Abf;
    const int K2 = K >> 1;

    const int tid   = threadIdx.x;
    const int warp  = tid >> 5, lane = tid & 31;
    const int group = lane >> 2, tig = lane & 3;
    const int wm = (warp >> 2) * 64;
    const int wn = (warp & 3) * 32;
    const int m0 = blockIdx.y * 128, n0 = blockIdx.x * 128;

    // global->smem mappings (per thread: 2 uint4 for A, 2 for B)
    uint4 gA[2], gB[2];

    auto loadg = [&](int kt) {
        #pragma unroll
        for (int ld = 0; ld < 2; ld++) {
            int ia = ld * 256 + tid;
            int row = ia >> 2, p4 = ia & 3;
            gA[ld] = *(const uint4*)(A32 + (size_t)(m0 + row) * K2 + kt * 16 + p4 * 4);
            int p = (ia >> 3) & 15;
            int c = (ia & 7) | ((ia >> 7) << 3);
            gB[ld] = *(const uint4*)(Bp + (size_t)(kt * 16 + p) * N + n0 + c * 4);
        }
    };
    auto store_s = [&](int buf) {
        #pragma unroll
        for (int ld = 0; ld < 2; ld++) {
            int ia = ld * 256 + tid;
            int row = ia >> 2, p4 = ia & 3;
            *(uint4*)&As[buf][row][p4 * 4] = gA[ld];
            int p = (ia >> 3) & 15;
            int c = (ia & 7) | ((ia >> 7) << 3);
            *(uint4*)&Bs[buf][p][c * 4] = gB[ld];
        }
    };

    loadg(0);
    store_s(0);
    __syncthreads();

    float acc[4][4][4];
    #pragma unroll
    for (int mi = 0; mi < 4; mi++)
        #pragma unroll
        for (int ni = 0; ni < 4; ni++)
            #pragma unroll
            for (int r = 0; r < 4; r++) acc[mi][ni][r] = 0.f;

    const int nk = K / 32;
    for (int kt = 0; kt < nk; kt++) {
        const int buf = kt & 1;
        const bool pf = (kt + 1 < nk);
        if (pf) loadg(kt + 1);

        #pragma unroll
        for (int k16 = 0; k16 < 2; k16++) {
            const int kr0 = k16 * 8 + tig, kr1 = kr0 + 4;
            uint32_t a[4][4], b[4][2];
            #pragma unroll
            for (int mi = 0; mi < 4; mi++) {
                int mm = wm + mi * 16 + group;
                a[mi][0] = As[buf][mm][kr0];
                a[mi][1] = As[buf][mm + 8][kr0];
                a[mi][2] = As[buf][mm][kr1];
                a[mi][3] = As[buf][mm + 8][kr1];
            }
            #pragma unroll
            for (int ni = 0; ni < 4; ni++) {
                int nn = wn + ni * 8 + group;
                b[ni][0] = Bs[buf][kr0][nn];
                b[ni][1] = Bs[buf][kr1][nn];
            }
            #pragma unroll
            for (int mi = 0; mi < 4; mi++)
                #pragma unroll
                for (int ni = 0; ni < 4; ni++) {
                    asm volatile(
                        "mma.sync.aligned.m16n8k16.row.col.f32.bf16.bf16.f32 "
                        "{%0,%1,%2,%3}, {%4,%5,%6,%7}, {%8,%9}, {%0,%1,%2,%3};"
                        : "+f"(acc[mi][ni][0]), "+f"(acc[mi][ni][1]),
                          "+f"(acc[mi][ni][2]), "+f"(acc[mi][ni][3])
                        : "r"(a[mi][0]), "r"(a[mi][1]), "r"(a[mi][2]), "r"(a[mi][3]),
                          "r"(b[ni][0]), "r"(b[ni][1]));
                }
        }

        if (pf) store_s(buf ^ 1);
        __syncthreads();
    }

    // epilogue
    #pragma unroll
    for (int mi = 0; mi < 4; mi++) {
        #pragma unroll
        for (int half = 0; half < 2; half++) {
            int m = m0 + wm + mi * 16 + group + half * 8;
            #pragma unroll
            for (int ni = 0; ni < 4; ni++) {
                int n = n0 + wn + ni * 8 + tig * 2;
                float v0 = acc[mi][ni][half * 2 + 0];
                float v1 = acc[mi][ni][half * 2 + 1];
                if (EPI != EPI_NONE) { v0 += bias[n]; v1 += bias[n + 1]; }
                if (EPI == EPI_GELU) {
                    v0 = 0.5f * v0 * (1.0f + erff(v0 * 0.70710678118654752f));
                    v1 = 0.5f * v1 * (1.0f + erff(v1 * 0.70710678118654752f));
                } else if (EPI == EPI_SIG) {
                    v0 = 1.0f / (1.0f + __expf(-v0));
                    v1 = 1.0f / (1.0f + __expf(-v1));
                } else if (EPI == EPI_RES) {
                    v0 += res[(size_t)m * N + n];
                    v1 += res[(size_t)m * N + n + 1];
                }
                if (OBF) {
                    __nv_bfloat162 h2 = __floats2bfloat162_rn(v0, v1);
                    *(__nv_bfloat162*)((__nv_bfloat16*)Cout + (size_t)m * N + n) = h2;
                } else {
                    *(float2*)((float*)Cout + (size_t)m * N + n) = make_float2(v0, v1);
                }
            }
        }
    }
}

// ---------------- attention: 1 block per (b,p,h), 256 threads -------------
// qkv fp32 in, out bf16 (feeds o-proj GEMM A-side)
__global__ __launch_bounds__(256)
void attn_k(const float* __restrict__ qkv, __nv_bfloat16* __restrict__ out)
{
    extern __shared__ float sm[];
    float* Ks = sm;
    float* Vs = sm + NN * DHEAD;
    int bid = blockIdx.x;
    int h  = bid & 7;
    int bp = bid >> 3;
    int tbase = bp * NN;
    int hoff = h * DHEAD;

    for (int idx = threadIdx.x; idx < NN * DHEAD; idx += 256) {
        int r = idx >> 6, c = idx & 63;
        size_t g = (size_t)(tbase + r) * (3 * DIM);
        Ks[idx] = qkv[g + DIM     + hoff + c];
        Vs[idx] = qkv[g + 2 * DIM + hoff + c];
    }
    __syncthreads();

    int t = tbase + threadIdx.x;
    float q[64];
    {
        const float4* qp = (const float4*)(qkv + (size_t)t * (3 * DIM) + hoff);
        #pragma unroll
        for (int i = 0; i < 16; i++) {
            float4 v = qp[i];
            q[4*i] = v.x; q[4*i+1] = v.y; q[4*i+2] = v.z; q[4*i+3] = v.w;
        }
    }
    const float scale = 0.125f;

    float m = -1e30f;
    for (int j = 0; j < NN; j++) {
        const float4* kp = (const float4*)(Ks + j * 64);
        float s = 0.f;
        #pragma unroll
        for (int i = 0; i < 16; i++) {
            float4 kv = kp[i];
            s += q[4*i]*kv.x + q[4*i+1]*kv.y + q[4*i+2]*kv.z + q[4*i+3]*kv.w;
        }
        m = fmaxf(m, s * scale);
    }

    float o[64];
    #pragma unroll
    for (int i = 0; i < 64; i++) o[i] = 0.f;
    float l = 0.f;
    for (int j = 0; j < NN; j++) {
        const float4* kp = (const float4*)(Ks + j * 64);
        float s = 0.f;
        #pragma unroll
        for (int i = 0; i < 16; i++) {
            float4 kv = kp[i];
            s += q[4*i]*kv.x + q[4*i+1]*kv.y + q[4*i+2]*kv.z + q[4*i+3]*kv.w;
        }
        float p = __expf(s * scale - m);
        l += p;
        const float4* vp = (const float4*)(Vs + j * 64);
        #pragma unroll
        for (int i = 0; i < 16; i++) {
            float4 vv = vp[i];
            o[4*i]   += p * vv.x;
            o[4*i+1] += p * vv.y;
            o[4*i+2] += p * vv.z;
            o[4*i+3] += p * vv.w;
        }
    }
    float inv = 1.0f / l;
    __nv_bfloat162* op = (__nv_bfloat162*)(out + (size_t)t * DIM + hoff);
    #pragma unroll
    for (int i = 0; i < 16; i++) {
        op[2*i]   = __floats2bfloat162_rn(o[4*i]   * inv, o[4*i+1] * inv);
        op[2*i+1] = __floats2bfloat162_rn(o[4*i+2] * inv, o[4*i+3] * inv);
    }
}

// ---------------- biattn pieces ----------------
__global__ void mean_k(const __nv_bfloat16* __restrict__ bx, __nv_bfloat16* __restrict__ xg)
{
    int idx = blockIdx.x * blockDim.x + threadIdx.x;
    if (idx >= BB * NN * DIM) return;
    int d = idx % DIM;
    int n = (idx / DIM) % NN;
    int b = idx / (DIM * NN);
    size_t base = ((size_t)(b * PP) * NN + n) * DIM + d;
    const size_t st = (size_t)NN * DIM;
    float s = __bfloat162float(bx[base]) + __bfloat162float(bx[base + st])
            + __bfloat162float(bx[base + 2*st]) + __bfloat162float(bx[base + 3*st]);
    xg[idx] = __float2bfloat16(0.25f * s);
}

__global__ __launch_bounds__(256)
void sattn_k(const __nv_bfloat16* __restrict__ xl, const __nv_bfloat16* __restrict__ xga,
             const float* __restrict__ ws, const float* __restrict__ bsc,
             float* __restrict__ sa)
{
    int gtid = blockIdx.x * 256 + threadIdx.x;
    int t = gtid >> 5;
    int lane = threadIdx.x & 31;
    if (t >= TT) return;
    int b = t / (PP * NN);
    int n = t % NN;
    const __nv_bfloat16* xlp = xl  + (size_t)t * RED;
    const __nv_bfloat16* xgp = xga + ((size_t)b * NN + n) * RED;
    float s = 0.f;
    for (int i = lane; i < RED; i += 32)
        s += __bfloat162float(xlp[i]) * ws[i] + __bfloat162float(xgp[i]) * ws[RED + i];
    #pragma unroll
    for (int o = 16; o; o >>= 1) s += __shfl_xor_sync(0xffffffffu, s, o);
    if (lane == 0) sa[t] = 1.0f / (1.0f + __expf(-(s + bsc[0])));
}

// out[idx] = x[idx] + h[idx]*ca*sa   (out may alias x, or be d_out on last layer)
__global__ void fuse_k(const float* __restrict__ h, const float* __restrict__ ca,
                       const float* __restrict__ sa, const float* __restrict__ x,
                       float* __restrict__ out)
{
    int idx = blockIdx.x * blockDim.x + threadIdx.x;
    if (idx >= TT * DIM) return;
    int t = idx / DIM;
    int d = idx % DIM;
    int b = t / (PP * NN);
    int n = t % NN;
    out[idx] = x[idx] + h[idx] * ca[((size_t)b * NN + n) * DIM + d] * sa[t];
}

// ---------------- host driver ----------------
extern "C" void kernel_launch(void* const* d_in, const int* in_sizes, int n_in,
                              void* d_out, int out_size)
{
    const float* x_in  = (const float*)d_in[0];
    const float* ln1_g = (const float*)d_in[1];
    const float* ln1_b = (const float*)d_in[2];
    const float* w_qkv = (const float*)d_in[3];
    const float* w_o   = (const float*)d_in[4];
    const float* b_o   = (const float*)d_in[5];
    const float* ln2_g = (const float*)d_in[6];
    const float* ln2_b = (const float*)d_in[7];
    const float* w1    = (const float*)d_in[8];
    const float* b1    = (const float*)d_in[9];
    const float* w2    = (const float*)d_in[10];
    const float* b2    = (const float*)d_in[11];
    const float* bn_g  = (const float*)d_in[12];
    const float* bn_b  = (const float*)d_in[13];
    const float* wg    = (const float*)d_in[14];
    const float* bg    = (const float*)d_in[15];
    const float* wl    = (const float*)d_in[16];
    const float* bl    = (const float*)d_in[17];
    const float* wc    = (const float*)d_in[18];
    const float* bc    = (const float*)d_in[19];
    const float* ws    = (const float*)d_in[20];
    const float* bs    = (const float*)d_in[21];

    float* base = nullptr;
    cudaGetSymbolAddress((void**)&base, g_scratch);
    float*          X   = base + OFF_X;
    __nv_bfloat16*  Y   = (__nv_bfloat16*)(base + OFF_Y);
    float*          QKV = base + OFF_QKV;
    __nv_bfloat16*  ATT = (__nv_bfloat16*)(base + OFF_ATT);
    __nv_bfloat16*  H1  = (__nv_bfloat16*)(base + OFF_H1);
    float*          H   = base + OFF_H;
    __nv_bfloat16*  BX  = (__nv_bfloat16*)(base + OFF_BX);
    __nv_bfloat16*  XG  = (__nv_bfloat16*)(base + OFF_XG);
    __nv_bfloat16*  XGA = (__nv_bfloat16*)(base + OFF_XGA);
    __nv_bfloat16*  XL  = (__nv_bfloat16*)(base + OFF_XL);
    float*          CA  = base + OFF_CA;
    float*          SA  = base + OFF_SA;
    uint32_t*       WP  = (uint32_t*)(base + OFF_WP);

    const int ATTN_SMEM = 2 * NN * DHEAD * sizeof(float);   // 128 KB
    cudaFuncSetAttribute((const void*)attn_k,
                         cudaFuncAttributeMaxDynamicSharedMemorySize, ATTN_SMEM);

    const int EW = 256;

    // pack all weights to bf16x2 pair layout (once per launch, ~20us)
    {
        int t;
        t = 4*256*1536; packw_k<<<(t+EW-1)/EW, EW>>>(w_qkv, WP+WP_QKV,  512, 1536, t);
        t = 4*256*512;  packw_k<<<(t+EW-1)/EW, EW>>>(w_o,   WP+WP_O,    512,  512, t);
        t = 4*256*2048; packw_k<<<(t+EW-1)/EW, EW>>>(w1,    WP+WP_W1,   512, 2048, t);
        t = 4*1024*512; packw_k<<<(t+EW-1)/EW, EW>>>(w2,    WP+WP_W2,  2048,  512, t);
        t = 4*256*128;  packw_k<<<(t+EW-1)/EW, EW>>>(wg,    WP+WP_WG,   512,  128, t);
        t = 4*256*128;  packw_k<<<(t+EW-1)/EW, EW>>>(wl,    WP+WP_WL,   512,  128, t);
        t = 4*64*512;   packw_k<<<(t+EW-1)/EW, EW>>>(wc,    WP+WP_WC,   128,  512, t);
    }

    for (int l = 0; l < DEPTH; l++) {
        const float* Xin = (l == 0) ? x_in : X;   // residual stream source

        // ---- attention half ----
        ln_k<<<TT, 128>>>(Xin, Y, ln1_g + l*DIM, ln1_b + l*DIM);
        bgemm_k<EPI_NONE,0><<<dim3(3*DIM/128, TT/128), 256>>>(
            Y, WP + WP_QKV + (size_t)l*256*1536, QKV, TT, 3*DIM, DIM, nullptr, nullptr);
        attn_k<<<BB*PP*HEADS, 256, ATTN_SMEM>>>(QKV, ATT);
        bgemm_k<EPI_RES,0><<<dim3(DIM/128, TT/128), 256>>>(
            ATT, WP + WP_O + (size_t)l*256*512, X, TT, DIM, DIM, b_o + l*DIM, Xin);

        // ---- mlp half ----
        ln_k<<<TT, 128>>>(X, Y, ln2_g + l*DIM, ln2_b + l*DIM);
        bgemm_k<EPI_GELU,1><<<dim3(MLPD/128, TT/128), 256>>>(
            Y, WP + WP_W1 + (size_t)l*256*2048, H1, TT, MLPD, DIM, b1 + l*MLPD, nullptr);
        bgemm_k<EPI_BIAS,0><<<dim3(DIM/128, TT/128), 256>>>(
            H1, WP + WP_W2 + (size_t)l*1024*512, H, TT, DIM, MLPD, b2 + l*DIM, nullptr);

        // ---- biattn ----
        ln_k<<<TT, 128>>>(H, BX, bn_g + l*DIM, bn_b + l*DIM);
        mean_k<<<(BB*NN*DIM + EW - 1) / EW, EW>>>(BX, XG);
        bgemm_k<EPI_GELU,1><<<dim3(RED/128, BB*NN/128), 256>>>(
            XG, WP + WP_WG + (size_t)l*256*128, XGA, BB*NN, RED, DIM, bg + l*RED, nullptr);
        bgemm_k<EPI_GELU,1><<<dim3(RED/128, TT/128), 256>>>(
            BX, WP + WP_WL + (size_t)l*256*128, XL, TT, RED, DIM, bl + l*RED, nullptr);
        bgemm_k<EPI_SIG,0><<<dim3(DIM/128, BB*NN/128), 256>>>(
            XGA, WP + WP_WC + (size_t)l*64*512, CA, BB*NN, DIM, RED, bc + l*DIM, nullptr);
        sattn_k<<<(TT*32 + 255) / 256, 256>>>(XL, XGA, ws + l*2*RED, bs + l, SA);

        float* fuse_out = (l == DEPTH - 1) ? (float*)d_out : X;
        fuse_k<<<(TT*DIM + EW - 1) / EW, EW>>>(H, CA, SA, X, fuse_out);
    }
}

// round 14
// speedup vs baseline: 2.2857x; 1.6147x over previous
#include <cuda_runtime.h>
#include <cuda_bf16.h>
#include <cstdint>

// ---------------- problem constants ----------------
#define DEPTH  4
#define HEADS  8
#define DHEAD  64
#define DIM    512
#define MLPD   2048
#define RED    128
#define BB     8
#define PP     4
#define NN     256
#define TT     (BB*PP*NN)     // 8192 tokens

// ---------------- scratch ----------------
static const size_t OFF_X   = 0;                               // f32 residual
static const size_t OFF_Y   = OFF_X   + (size_t)TT*DIM;        // bf16 LN out
static const size_t OFF_QKV = OFF_Y   + (size_t)TT*DIM;        // bf16 now
static const size_t OFF_ATT = OFF_QKV + (size_t)TT*3*DIM;      // bf16
static const size_t OFF_H1  = OFF_ATT + (size_t)TT*DIM;        // bf16
static const size_t OFF_H   = OFF_H1  + (size_t)TT*MLPD;       // f32
static const size_t OFF_BX  = OFF_H   + (size_t)TT*DIM;        // bf16
static const size_t OFF_XG  = OFF_BX  + (size_t)TT*DIM;        // bf16
static const size_t OFF_XGA = OFF_XG  + (size_t)BB*NN*DIM;     // bf16
static const size_t OFF_XL  = OFF_XGA + (size_t)BB*NN*RED;     // bf16
static const size_t OFF_CA  = OFF_XL  + (size_t)TT*RED;        // f32
static const size_t OFF_SA  = OFF_CA  + (size_t)BB*NN*DIM;     // f32
static const size_t OFF_WP  = OFF_SA  + TT;                    // packed bf16x2 weights

static const size_t WP_QKV = 0;
static const size_t WP_O   = WP_QKV + (size_t)4*256*1536;
static const size_t WP_W1  = WP_O   + (size_t)4*256*512;
static const size_t WP_W2  = WP_W1  + (size_t)4*256*2048;
static const size_t WP_WG  = WP_W2  + (size_t)4*1024*512;
static const size_t WP_WL  = WP_WG  + (size_t)4*256*128;
static const size_t WP_WC  = WP_WL  + (size_t)4*256*128;
static const size_t WP_TOT = WP_WC  + (size_t)4*64*512;

static const size_t SCRATCH_FLOATS = OFF_WP + WP_TOT;

__device__ float g_scratch[SCRATCH_FLOATS];

// ---------------- helpers ----------------
__device__ __forceinline__ uint32_t smem_u32(const void* p) {
    uint32_t a;
    asm("{ .reg .u64 t; cvta.to.shared.u64 t, %1; cvt.u32.u64 %0, t; }" : "=r"(a) : "l"(p));
    return a;
}
__device__ __forceinline__ uint32_t packbf(float x, float y) {
    __nv_bfloat162 h = __floats2bfloat162_rn(x, y);
    return *reinterpret_cast<uint32_t*>(&h);
}
// verified swizzled tile layout: row r, 16B chunk c (0..3), 64B per row
__device__ __forceinline__ uint32_t tile_off(int r, int c) {
    return (uint32_t)((r >> 1) * 128 + (((4 * (r & 1) + c) ^ ((r >> 1) & 7)) * 16));
}

// pack fp32 weights [D][K][N] -> bf16x2 pairs along K: Wp[(d*(K/2)+p)*N + n]
__global__ void packw_k(const float* __restrict__ W, uint32_t* __restrict__ Wp,
                        int K, int N, int total)
{
    int idx = blockIdx.x * blockDim.x + threadIdx.x;
    if (idx >= total) return;
    int n  = idx % N;
    int rp = idx / N;
    int p  = rp % (K >> 1);
    int d  = rp / (K >> 1);
    const float* s = W + ((size_t)d * K + 2 * p) * N + n;
    __nv_bfloat162 h = __floats2bfloat162_rn(s[0], s[N]);
    ((__nv_bfloat162*)Wp)[idx] = h;
}

// ---------------- layernorm: fp32 in, bf16 out ----------------
__global__ __launch_bounds__(128)
void ln_k(const float* __restrict__ in, __nv_bfloat16* __restrict__ out,
          const float* __restrict__ g, const float* __restrict__ b)
{
    int t = blockIdx.x;
    int lane = threadIdx.x & 31, w = threadIdx.x >> 5;
    float4 v = ((const float4*)(in + (size_t)t*DIM))[threadIdx.x];
    float s = v.x + v.y + v.z + v.w;
    float q = v.x*v.x + v.y*v.y + v.z*v.z + v.w*v.w;
    #pragma unroll
    for (int o = 16; o; o >>= 1) {
        s += __shfl_xor_sync(0xffffffffu, s, o);
        q += __shfl_xor_sync(0xffffffffu, q, o);
    }
    __shared__ float ss[4], qq[4];
    if (lane == 0) { ss[w] = s; qq[w] = q; }
    __syncthreads();
    s = ss[0] + ss[1] + ss[2] + ss[3];
    q = qq[0] + qq[1] + qq[2] + qq[3];
    float mean = s * (1.0f / DIM);
    float var  = q * (1.0f / DIM) - mean * mean;
    float inv  = rsqrtf(var + 1e-5f);
    float4 gg = ((const float4*)g)[threadIdx.x];
    float4 bb = ((const float4*)b)[threadIdx.x];
    float o0 = (v.x - mean) * inv * gg.x + bb.x;
    float o1 = (v.y - mean) * inv * gg.y + bb.y;
    float o2 = (v.z - mean) * inv * gg.z + bb.z;
    float o3 = (v.w - mean) * inv * gg.w + bb.w;
    __nv_bfloat162* op = (__nv_bfloat162*)(out + (size_t)t*DIM) + 2*threadIdx.x;
    op[0] = __floats2bfloat162_rn(o0, o1);
    op[1] = __floats2bfloat162_rn(o2, o3);
}

// ---------------- bf16 tensor-core GEMM (proven round-7 mainloop) ---------
#define EPI_NONE 0
#define EPI_BIAS 1
#define EPI_GELU 2
#define EPI_SIG  3
#define EPI_RES  4

#define ASTR 20
#define BSTR 136

template<int EPI, int OBF>
__global__ __launch_bounds__(256, 2)
void bgemm_k(const __nv_bfloat16* __restrict__ Abf, const uint32_t* __restrict__ Bp,
             void* __restrict__ Cout, int M, int N, int K,
             const float* __restrict__ bias, const float* __restrict__ res)
{
    __shared__ uint32_t As[2][128][ASTR];
    __shared__ uint32_t Bs[2][16][BSTR];

    const uint32_t* A32 = (const uint32_t*)Abf;
    const int K2 = K >> 1;

    const int tid   = threadIdx.x;
    const int warp  = tid >> 5, lane = tid & 31;
    const int group = lane >> 2, tig = lane & 3;
    const int wm = (warp >> 2) * 64;
    const int wn = (warp & 3) * 32;
    const int m0 = blockIdx.y * 128, n0 = blockIdx.x * 128;

    uint4 gA[2], gB[2];

    auto loadg = [&](int kt) {
        #pragma unroll
        for (int ld = 0; ld < 2; ld++) {
            int ia = ld * 256 + tid;
            int row = ia >> 2, p4 = ia & 3;
            gA[ld] = *(const uint4*)(A32 + (size_t)(m0 + row) * K2 + kt * 16 + p4 * 4);
            int p = (ia >> 3) & 15;
            int c = (ia & 7) | ((ia >> 7) << 3);
            gB[ld] = *(const uint4*)(Bp + (size_t)(kt * 16 + p) * N + n0 + c * 4);
        }
    };
    auto store_s = [&](int buf) {
        #pragma unroll
        for (int ld = 0; ld < 2; ld++) {
            int ia = ld * 256 + tid;
            int row = ia >> 2, p4 = ia & 3;
            *(uint4*)&As[buf][row][p4 * 4] = gA[ld];
            int p = (ia >> 3) & 15;
            int c = (ia & 7) | ((ia >> 7) << 3);
            *(uint4*)&Bs[buf][p][c * 4] = gB[ld];
        }
    };

    loadg(0);
    store_s(0);
    __syncthreads();

    float acc[4][4][4];
    #pragma unroll
    for (int mi = 0; mi < 4; mi++)
        #pragma unroll
        for (int ni = 0; ni < 4; ni++)
            #pragma unroll
            for (int r = 0; r < 4; r++) acc[mi][ni][r] = 0.f;

    const int nk = K / 32;
    for (int kt = 0; kt < nk; kt++) {
        const int buf = kt & 1;
        const bool pf = (kt + 1 < nk);
        if (pf) loadg(kt + 1);

        #pragma unroll
        for (int k16 = 0; k16 < 2; k16++) {
            const int kr0 = k16 * 8 + tig, kr1 = kr0 + 4;
            uint32_t a[4][4], b[4][2];
            #pragma unroll
            for (int mi = 0; mi < 4; mi++) {
                int mm = wm + mi * 16 + group;
                a[mi][0] = As[buf][mm][kr0];
                a[mi][1] = As[buf][mm + 8][kr0];
                a[mi][2] = As[buf][mm][kr1];
                a[mi][3] = As[buf][mm + 8][kr1];
            }
            #pragma unroll
            for (int ni = 0; ni < 4; ni++) {
                int nn = wn + ni * 8 + group;
                b[ni][0] = Bs[buf][kr0][nn];
                b[ni][1] = Bs[buf][kr1][nn];
            }
            #pragma unroll
            for (int mi = 0; mi < 4; mi++)
                #pragma unroll
                for (int ni = 0; ni < 4; ni++) {
                    asm volatile(
                        "mma.sync.aligned.m16n8k16.row.col.f32.bf16.bf16.f32 "
                        "{%0,%1,%2,%3}, {%4,%5,%6,%7}, {%8,%9}, {%0,%1,%2,%3};"
                        : "+f"(acc[mi][ni][0]), "+f"(acc[mi][ni][1]),
                          "+f"(acc[mi][ni][2]), "+f"(acc[mi][ni][3])
                        : "r"(a[mi][0]), "r"(a[mi][1]), "r"(a[mi][2]), "r"(a[mi][3]),
                          "r"(b[ni][0]), "r"(b[ni][1]));
                }
        }

        if (pf) store_s(buf ^ 1);
        __syncthreads();
    }

    #pragma unroll
    for (int mi = 0; mi < 4; mi++) {
        #pragma unroll
        for (int half = 0; half < 2; half++) {
            int m = m0 + wm + mi * 16 + group + half * 8;
            #pragma unroll
            for (int ni = 0; ni < 4; ni++) {
                int n = n0 + wn + ni * 8 + tig * 2;
                float v0 = acc[mi][ni][half * 2 + 0];
                float v1 = acc[mi][ni][half * 2 + 1];
                if (EPI != EPI_NONE) { v0 += bias[n]; v1 += bias[n + 1]; }
                if (EPI == EPI_GELU) {
                    v0 = 0.5f * v0 * (1.0f + erff(v0 * 0.70710678118654752f));
                    v1 = 0.5f * v1 * (1.0f + erff(v1 * 0.70710678118654752f));
                } else if (EPI == EPI_SIG) {
                    v0 = 1.0f / (1.0f + __expf(-v0));
                    v1 = 1.0f / (1.0f + __expf(-v1));
                } else if (EPI == EPI_RES) {
                    v0 += res[(size_t)m * N + n];
                    v1 += res[(size_t)m * N + n + 1];
                }
                if (OBF) {
                    __nv_bfloat162 h2 = __floats2bfloat162_rn(v0, v1);
                    *(__nv_bfloat162*)((__nv_bfloat16*)Cout + (size_t)m * N + n) = h2;
                } else {
                    *(float2*)((float*)Cout + (size_t)m * N + n) = make_float2(v0, v1);
                }
            }
        }
    }
}

// ---------------- flash attention (tensor cores) --------------------------
// One CTA per (b,p,h). qkv bf16 [token][1536]. out bf16 [token][512].
// smem: Q 2x(256x32) @ 0, K 2x(256x32) @ 32768, Vt 8x(64x32) @ 65536. 96KB.
#define AQ_OFF 0
#define AK_OFF 32768
#define AV_OFF 65536
#define ATT2_SMEM (96*1024)

__global__ __launch_bounds__(256)
void attn2_k(const __nv_bfloat16* __restrict__ qkv, __nv_bfloat16* __restrict__ out)
{
    extern __shared__ __align__(1024) uint8_t sm8[];
    const uint32_t sb = smem_u32(sm8);
    const int tid = threadIdx.x;
    const int h = blockIdx.x & 7, bp = blockIdx.x >> 3;
    const int tbase = bp * NN, hoff = h * DHEAD;

    // stage Q, K (chunked 32-k tiles, verified swizzle)
    for (int idx = tid; idx < 2048; idx += 256) {
        int r = idx >> 3, u = idx & 7;
        int q = u >> 2, c = u & 3;
        const __nv_bfloat16* rowp = qkv + (size_t)(tbase + r) * 1536;
        *(uint4*)(sm8 + AQ_OFF + q * 16384 + tile_off(r, c)) =
            *(const uint4*)(rowp + hoff + q * 32 + c * 8);
        *(uint4*)(sm8 + AK_OFF + q * 16384 + tile_off(r, c)) =
            *(const uint4*)(rowp + 512 + hoff + q * 32 + c * 8);
    }
    // stage V transposed: Vt[d][kv], 8 chunks of 32 kv
    for (int idx = tid; idx < 2048; idx += 256) {
        int r = idx >> 3, u = idx & 7;          // r = kv, u = d-octet
        uint4 v = *(const uint4*)(qkv + (size_t)(tbase + r) * 1536 + 1024 + hoff + u * 8);
        const __nv_bfloat16* pv = (const __nv_bfloat16*)&v;
        int chunk = r >> 5, col = r & 31, cc = col >> 3, wi = col & 7;
        #pragma unroll
        for (int j = 0; j < 8; j++) {
            int d = u * 8 + j;
            uint32_t a = AV_OFF + chunk * 4096 + (d >> 1) * 128
                       + (((4 * (d & 1) + cc) ^ ((d >> 1) & 7)) * 16) + wi * 2;
            *(__nv_bfloat16*)(sm8 + a) = pv[j];
        }
    }
    __syncthreads();

    const int warp = tid >> 5, lane = tid & 31;
    const int g = lane >> 2, t4 = lane & 3;
    const int R = warp * 32;
    const int laneA = (lane & 7) + ((lane >> 3) & 1) * 8;   // A frag rows
    const int cA    = (lane >> 4) & 1;
    const int laneB = (lane & 7) + ((lane >> 4) & 1) * 8;   // B frag rows
    const int cBi   = (lane >> 3) & 1;

    float mrow[2][2], lrow[2][2];
    float o[2][8][4];
    #pragma unroll
    for (int mi = 0; mi < 2; mi++)
        #pragma unroll
        for (int hf = 0; hf < 2; hf++) { mrow[mi][hf] = -1e30f; lrow[mi][hf] = 0.f; }
    #pragma unroll
    for (int mi = 0; mi < 2; mi++)
        #pragma unroll
        for (int ni = 0; ni < 8; ni++)
            #pragma unroll
            for (int r = 0; r < 4; r++) o[mi][ni][r] = 0.f;

    for (int blk = 0; blk < 4; blk++) {
        // ---- S = Q @ K^T over this 64-kv block ----
        float s[2][8][4];
        #pragma unroll
        for (int mi = 0; mi < 2; mi++)
            #pragma unroll
            for (int ni = 0; ni < 8; ni++)
                #pragma unroll
                for (int r = 0; r < 4; r++) s[mi][ni][r] = 0.f;

        #pragma unroll
        for (int st = 0; st < 4; st++) {
            const int q = st >> 1;
            const uint32_t ko = (uint32_t)((st & 1) * 32);
            uint32_t a[2][4], bk[8][2];
            #pragma unroll
            for (int mi = 0; mi < 2; mi++) {
                uint32_t ad = (sb + AQ_OFF + q * 16384 + tile_off(R + mi * 16 + laneA, cA)) ^ ko;
                asm volatile(
                    "ldmatrix.sync.aligned.m8n8.x4.shared.b16 {%0,%1,%2,%3}, [%4];"
                    : "=r"(a[mi][0]), "=r"(a[mi][1]), "=r"(a[mi][2]), "=r"(a[mi][3])
                    : "r"(ad));
            }
            #pragma unroll
            for (int p = 0; p < 4; p++) {
                uint32_t ad = (sb + AK_OFF + q * 16384 + tile_off(blk * 64 + p * 16 + laneB, cBi)) ^ ko;
                asm volatile(
                    "ldmatrix.sync.aligned.m8n8.x4.shared.b16 {%0,%1,%2,%3}, [%4];"
                    : "=r"(bk[2*p][0]), "=r"(bk[2*p][1]), "=r"(bk[2*p+1][0]), "=r"(bk[2*p+1][1])
                    : "r"(ad));
            }
            #pragma unroll
            for (int mi = 0; mi < 2; mi++)
                #pragma unroll
                for (int ni = 0; ni < 8; ni++) {
                    asm volatile(
                        "mma.sync.aligned.m16n8k16.row.col.f32.bf16.bf16.f32 "
                        "{%0,%1,%2,%3}, {%4,%5,%6,%7}, {%8,%9}, {%0,%1,%2,%3};"
                        : "+f"(s[mi][ni][0]), "+f"(s[mi][ni][1]),
                          "+f"(s[mi][ni][2]), "+f"(s[mi][ni][3])
                        : "r"(a[mi][0]), "r"(a[mi][1]), "r"(a[mi][2]), "r"(a[mi][3]),
                          "r"(bk[ni][0]), "r"(bk[ni][1]));
                }
        }

        // ---- online softmax ----
        #pragma unroll
        for (int mi = 0; mi < 2; mi++)
            #pragma unroll
            for (int ni = 0; ni < 8; ni++)
                #pragma unroll
                for (int r = 0; r < 4; r++) s[mi][ni][r] *= 0.125f;

        #pragma unroll
        for (int mi = 0; mi < 2; mi++) {
            #pragma unroll
            for (int hf = 0; hf < 2; hf++) {
                float bm = -1e30f;
                #pragma unroll
                for (int ni = 0; ni < 8; ni++) {
                    bm = fmaxf(bm, s[mi][ni][hf*2]);
                    bm = fmaxf(bm, s[mi][ni][hf*2+1]);
                }
                bm = fmaxf(bm, __shfl_xor_sync(0xffffffffu, bm, 1));
                bm = fmaxf(bm, __shfl_xor_sync(0xffffffffu, bm, 2));
                float mnew = fmaxf(mrow[mi][hf], bm);
                float corr = __expf(mrow[mi][hf] - mnew);
                mrow[mi][hf] = mnew;
                float rs = 0.f;
                #pragma unroll
                for (int ni = 0; ni < 8; ni++) {
                    float e0 = __expf(s[mi][ni][hf*2]   - mnew);
                    float e1 = __expf(s[mi][ni][hf*2+1] - mnew);
                    s[mi][ni][hf*2]   = e0;
                    s[mi][ni][hf*2+1] = e1;
                    rs += e0 + e1;
                }
                rs += __shfl_xor_sync(0xffffffffu, rs, 1);
                rs += __shfl_xor_sync(0xffffffffu, rs, 2);
                lrow[mi][hf] = lrow[mi][hf] * corr + rs;
                #pragma unroll
                for (int ni = 0; ni < 8; ni++) {
                    o[mi][ni][hf*2]   *= corr;
                    o[mi][ni][hf*2+1] *= corr;
                }
            }
        }

        // ---- pack P into A fragments ----
        uint32_t pa[2][4][4];
        #pragma unroll
        for (int mi = 0; mi < 2; mi++)
            #pragma unroll
            for (int st = 0; st < 4; st++) {
                pa[mi][st][0] = packbf(s[mi][2*st][0],   s[mi][2*st][1]);
                pa[mi][st][1] = packbf(s[mi][2*st][2],   s[mi][2*st][3]);
                pa[mi][st][2] = packbf(s[mi][2*st+1][0], s[mi][2*st+1][1]);
                pa[mi][st][3] = packbf(s[mi][2*st+1][2], s[mi][2*st+1][3]);
            }

        // ---- O += P @ V ----
        #pragma unroll
        for (int st = 0; st < 4; st++) {
            const int vc = blk * 2 + (st >> 1);
            const uint32_t ko = (uint32_t)((st & 1) * 32);
            uint32_t vb[8][2];
            #pragma unroll
            for (int pd = 0; pd < 4; pd++) {
                uint32_t ad = (sb + AV_OFF + vc * 4096 + tile_off(pd * 16 + laneB, cBi)) ^ ko;
                asm volatile(
                    "ldmatrix.sync.aligned.m8n8.x4.shared.b16 {%0,%1,%2,%3}, [%4];"
                    : "=r"(vb[2*pd][0]), "=r"(vb[2*pd][1]), "=r"(vb[2*pd+1][0]), "=r"(vb[2*pd+1][1])
                    : "r"(ad));
            }
            #pragma unroll
            for (int mi = 0; mi < 2; mi++)
                #pragma unroll
                for (int di = 0; di < 8; di++) {
                    asm volatile(
                        "mma.sync.aligned.m16n8k16.row.col.f32.bf16.bf16.f32 "
                        "{%0,%1,%2,%3}, {%4,%5,%6,%7}, {%8,%9}, {%0,%1,%2,%3};"
                        : "+f"(o[mi][di][0]), "+f"(o[mi][di][1]),
                          "+f"(o[mi][di][2]), "+f"(o[mi][di][3])
                        : "r"(pa[mi][st][0]), "r"(pa[mi][st][1]),
                          "r"(pa[mi][st][2]), "r"(pa[mi][st][3]),
                          "r"(vb[di][0]), "r"(vb[di][1]));
                }
        }
    }

    // ---- epilogue: normalize, write bf16 ----
    #pragma unroll
    for (int mi = 0; mi < 2; mi++) {
        #pragma unroll
        for (int hf = 0; hf < 2; hf++) {
            int row = tbase + R + mi * 16 + g + hf * 8;
            float inv = 1.0f / lrow[mi][hf];
            #pragma unroll
            for (int ni = 0; ni < 8; ni++) {
                __nv_bfloat162 h2 = __floats2bfloat162_rn(o[mi][ni][hf*2] * inv,
                                                          o[mi][ni][hf*2+1] * inv);
                *(__nv_bfloat162*)(out + (size_t)row * DIM + hoff + ni * 8 + t4 * 2) = h2;
            }
        }
    }
}

// ---------------- biattn pieces ----------------
__global__ void mean_k(const __nv_bfloat16* __restrict__ bx, __nv_bfloat16* __restrict__ xg)
{
    int idx = blockIdx.x * blockDim.x + threadIdx.x;
    if (idx >= BB * NN * DIM) return;
    int d = idx % DIM;
    int n = (idx / DIM) % NN;
    int b = idx / (DIM * NN);
    size_t base = ((size_t)(b * PP) * NN + n) * DIM + d;
    const size_t st = (size_t)NN * DIM;
    float s = __bfloat162float(bx[base]) + __bfloat162float(bx[base + st])
            + __bfloat162float(bx[base + 2*st]) + __bfloat162float(bx[base + 3*st]);
    xg[idx] = __float2bfloat16(0.25f * s);
}

__global__ __launch_bounds__(256)
void sattn_k(const __nv_bfloat16* __restrict__ xl, const __nv_bfloat16* __restrict__ xga,
             const float* __restrict__ ws, const float* __restrict__ bsc,
             float* __restrict__ sa)
{
    int gtid = blockIdx.x * 256 + threadIdx.x;
    int t = gtid >> 5;
    int lane = threadIdx.x & 31;
    if (t >= TT) return;
    int b = t / (PP * NN);
    int n = t % NN;
    const __nv_bfloat16* xlp = xl  + (size_t)t * RED;
    const __nv_bfloat16* xgp = xga + ((size_t)b * NN + n) * RED;
    float s = 0.f;
    for (int i = lane; i < RED; i += 32)
        s += __bfloat162float(xlp[i]) * ws[i] + __bfloat162float(xgp[i]) * ws[RED + i];
    #pragma unroll
    for (int o = 16; o; o >>= 1) s += __shfl_xor_sync(0xffffffffu, s, o);
    if (lane == 0) sa[t] = 1.0f / (1.0f + __expf(-(s + bsc[0])));
}

__global__ void fuse_k(const float* __restrict__ h, const float* __restrict__ ca,
                       const float* __restrict__ sa, const float* __restrict__ x,
                       float* __restrict__ out)
{
    int idx = blockIdx.x * blockDim.x + threadIdx.x;
    if (idx >= TT * DIM) return;
    int t = idx / DIM;
    int d = idx % DIM;
    int b = t / (PP * NN);
    int n = t % NN;
    out[idx] = x[idx] + h[idx] * ca[((size_t)b * NN + n) * DIM + d] * sa[t];
}

// ---------------- host driver ----------------
extern "C" void kernel_launch(void* const* d_in, const int* in_sizes, int n_in,
                              void* d_out, int out_size)
{
    const float* x_in  = (const float*)d_in[0];
    const float* ln1_g = (const float*)d_in[1];
    const float* ln1_b = (const float*)d_in[2];
    const float* w_qkv = (const float*)d_in[3];
    const float* w_o   = (const float*)d_in[4];
    const float* b_o   = (const float*)d_in[5];
    const float* ln2_g = (const float*)d_in[6];
    const float* ln2_b = (const float*)d_in[7];
    const float* w1    = (const float*)d_in[8];
    const float* b1    = (const float*)d_in[9];
    const float* w2    = (const float*)d_in[10];
    const float* b2    = (const float*)d_in[11];
    const float* bn_g  = (const float*)d_in[12];
    const float* bn_b  = (const float*)d_in[13];
    const float* wg    = (const float*)d_in[14];
    const float* bg    = (const float*)d_in[15];
    const float* wl    = (const float*)d_in[16];
    const float* bl    = (const float*)d_in[17];
    const float* wc    = (const float*)d_in[18];
    const float* bc    = (const float*)d_in[19];
    const float* ws    = (const float*)d_in[20];
    const float* bs    = (const float*)d_in[21];

    float* base = nullptr;
    cudaGetSymbolAddress((void**)&base, g_scratch);
    float*          X   = base + OFF_X;
    __nv_bfloat16*  Y   = (__nv_bfloat16*)(base + OFF_Y);
    __nv_bfloat16*  QKV = (__nv_bfloat16*)(base + OFF_QKV);
    __nv_bfloat16*  ATT = (__nv_bfloat16*)(base + OFF_ATT);
    __nv_bfloat16*  H1  = (__nv_bfloat16*)(base + OFF_H1);
    float*          H   = base + OFF_H;
    __nv_bfloat16*  BX  = (__nv_bfloat16*)(base + OFF_BX);
    __nv_bfloat16*  XG  = (__nv_bfloat16*)(base + OFF_XG);
    __nv_bfloat16*  XGA = (__nv_bfloat16*)(base + OFF_XGA);
    __nv_bfloat16*  XL  = (__nv_bfloat16*)(base + OFF_XL);
    float*          CA  = base + OFF_CA;
    float*          SA  = base + OFF_SA;
    uint32_t*       WP  = (uint32_t*)(base + OFF_WP);

    cudaFuncSetAttribute((const void*)attn2_k,
                         cudaFuncAttributeMaxDynamicSharedMemorySize, ATT2_SMEM);

    const int EW = 256;

    // pack all weights to bf16x2 pair layout (once per launch, ~30us)
    {
        int t;
        t = 4*256*1536; packw_k<<<(t+EW-1)/EW, EW>>>(w_qkv, WP+WP_QKV,  512, 1536, t);
        t = 4*256*512;  packw_k<<<(t+EW-1)/EW, EW>>>(w_o,   WP+WP_O,    512,  512, t);
        t = 4*256*2048; packw_k<<<(t+EW-1)/EW, EW>>>(w1,    WP+WP_W1,   512, 2048, t);
        t = 4*1024*512; packw_k<<<(t+EW-1)/EW, EW>>>(w2,    WP+WP_W2,  2048,  512, t);
        t = 4*256*128;  packw_k<<<(t+EW-1)/EW, EW>>>(wg,    WP+WP_WG,   512,  128, t);
        t = 4*256*128;  packw_k<<<(t+EW-1)/EW, EW>>>(wl,    WP+WP_WL,   512,  128, t);
        t = 4*64*512;   packw_k<<<(t+EW-1)/EW, EW>>>(wc,    WP+WP_WC,   128,  512, t);
    }

    for (int l = 0; l < DEPTH; l++) {
        const float* Xin = (l == 0) ? x_in : X;

        // ---- attention half ----
        ln_k<<<TT, 128>>>(Xin, Y, ln1_g + l*DIM, ln1_b + l*DIM);
        bgemm_k<EPI_NONE,1><<<dim3(3*DIM/128, TT/128), 256>>>(
            Y, WP + WP_QKV + (size_t)l*256*1536, QKV, TT, 3*DIM, DIM, nullptr, nullptr);
        attn2_k<<<BB*PP*HEADS, 256, ATT2_SMEM>>>(QKV, ATT);
        bgemm_k<EPI_RES,0><<<dim3(DIM/128, TT/128), 256>>>(
            ATT, WP + WP_O + (size_t)l*256*512, X, TT, DIM, DIM, b_o + l*DIM, Xin);

        // ---- mlp half ----
        ln_k<<<TT, 128>>>(X, Y, ln2_g + l*DIM, ln2_b + l*DIM);
        bgemm_k<EPI_GELU,1><<<dim3(MLPD/128, TT/128), 256>>>(
            Y, WP + WP_W1 + (size_t)l*256*2048, H1, TT, MLPD, DIM, b1 + l*MLPD, nullptr);
        bgemm_k<EPI_BIAS,0><<<dim3(DIM/128, TT/128), 256>>>(
            H1, WP + WP_W2 + (size_t)l*1024*512, H, TT, DIM, MLPD, b2 + l*DIM, nullptr);

        // ---- biattn ----
        ln_k<<<TT, 128>>>(H, BX, bn_g + l*DIM, bn_b + l*DIM);
        mean_k<<<(BB*NN*DIM + EW - 1) / EW, EW>>>(BX, XG);
        bgemm_k<EPI_GELU,1><<<dim3(RED/128, BB*NN/128), 256>>>(
            XG, WP + WP_WG + (size_t)l*256*128, XGA, BB*NN, RED, DIM, bg + l*RED, nullptr);
        bgemm_k<EPI_GELU,1><<<dim3(RED/128, TT/128), 256>>>(
            BX, WP + WP_WL + (size_t)l*256*128, XL, TT, RED, DIM, bl + l*RED, nullptr);
        bgemm_k<EPI_SIG,0><<<dim3(DIM/128, BB*NN/128), 256>>>(
            XGA, WP + WP_WC + (size_t)l*64*512, CA, BB*NN, DIM, RED, bc + l*DIM, nullptr);
        sattn_k<<<(TT*32 + 255) / 256, 256>>>(XL, XGA, ws + l*2*RED, bs + l, SA);

        float* fuse_out = (l == DEPTH - 1) ? (float*)d_out : X;
        fuse_k<<<(TT*DIM + EW - 1) / EW, EW>>>(H, CA, SA, X, fuse_out);
    }
}

// round 15
// speedup vs baseline: 2.4588x; 1.0757x over previous
#include <cuda_runtime.h>
#include <cuda_bf16.h>
#include <cstdint>

// ---------------- problem constants ----------------
#define DEPTH  4
#define HEADS  8
#define DHEAD  64
#define DIM    512
#define MLPD   2048
#define RED    128
#define BB     8
#define PP     4
#define NN     256
#define TT     (BB*PP*NN)     // 8192 tokens

// ---------------- scratch ----------------
static const size_t OFF_X   = 0;                               // f32 residual
static const size_t OFF_Y   = OFF_X   + (size_t)TT*DIM;        // bf16 LN out
static const size_t OFF_QKV = OFF_Y   + (size_t)TT*DIM;        // bf16
static const size_t OFF_ATT = OFF_QKV + (size_t)TT*3*DIM;      // bf16
static const size_t OFF_H1  = OFF_ATT + (size_t)TT*DIM;        // bf16
static const size_t OFF_H   = OFF_H1  + (size_t)TT*MLPD;       // f32
static const size_t OFF_BX  = OFF_H   + (size_t)TT*DIM;        // bf16
static const size_t OFF_XG  = OFF_BX  + (size_t)TT*DIM;        // bf16
static const size_t OFF_XGA = OFF_XG  + (size_t)BB*NN*DIM;     // bf16
static const size_t OFF_XL  = OFF_XGA + (size_t)BB*NN*RED;     // bf16
static const size_t OFF_CA  = OFF_XL  + (size_t)TT*RED;        // f32
static const size_t OFF_SA  = OFF_CA  + (size_t)BB*NN*DIM;     // f32
static const size_t OFF_WP  = OFF_SA  + TT;                    // packed bf16x2 weights

static const size_t WP_QKV = 0;
static const size_t WP_O   = WP_QKV + (size_t)4*256*1536;
static const size_t WP_W1  = WP_O   + (size_t)4*256*512;
static const size_t WP_W2  = WP_W1  + (size_t)4*256*2048;
static const size_t WP_WG  = WP_W2  + (size_t)4*1024*512;
static const size_t WP_WL  = WP_WG  + (size_t)4*256*128;
static const size_t WP_WC  = WP_WL  + (size_t)4*256*128;
static const size_t WP_TOT = WP_WC  + (size_t)4*64*512;

static const size_t SCRATCH_FLOATS = OFF_WP + WP_TOT;

__device__ float g_scratch[SCRATCH_FLOATS];

// ---------------- helpers ----------------
__device__ __forceinline__ uint32_t smem_u32(const void* p) {
    uint32_t a;
    asm("{ .reg .u64 t; cvta.to.shared.u64 t, %1; cvt.u32.u64 %0, t; }" : "=r"(a) : "l"(p));
    return a;
}
__device__ __forceinline__ void cp16(uint32_t dst, const void* src) {
    asm volatile("cp.async.cg.shared.global [%0], [%1], 16;\n" :: "r"(dst), "l"(src));
}
__device__ __forceinline__ void cp_commit() {
    asm volatile("cp.async.commit_group;\n");
}
template<int N>
__device__ __forceinline__ void cp_wait() {
    asm volatile("cp.async.wait_group %0;\n" :: "n"(N));
}
__device__ __forceinline__ uint32_t packbf(float x, float y) {
    __nv_bfloat162 h = __floats2bfloat162_rn(x, y);
    return *reinterpret_cast<uint32_t*>(&h);
}
// verified swizzled tile layout (flash attention): row r, 16B chunk c, 64B/row
__device__ __forceinline__ uint32_t tile_off(int r, int c) {
    return (uint32_t)((r >> 1) * 128 + (((4 * (r & 1) + c) ^ ((r >> 1) & 7)) * 16));
}

// pack fp32 weights [D][K][N] -> bf16x2 pairs along K: Wp[(d*(K/2)+p)*N + n]
__global__ void packw_k(const float* __restrict__ W, uint32_t* __restrict__ Wp,
                        int K, int N, int total)
{
    int idx = blockIdx.x * blockDim.x + threadIdx.x;
    if (idx >= total) return;
    int n  = idx % N;
    int rp = idx / N;
    int p  = rp % (K >> 1);
    int d  = rp / (K >> 1);
    const float* s = W + ((size_t)d * K + 2 * p) * N + n;
    __nv_bfloat162 h = __floats2bfloat162_rn(s[0], s[N]);
    ((__nv_bfloat162*)Wp)[idx] = h;
}

// ---------------- layernorm: fp32 in, bf16 out ----------------
__global__ __launch_bounds__(128)
void ln_k(const float* __restrict__ in, __nv_bfloat16* __restrict__ out,
          const float* __restrict__ g, const float* __restrict__ b)
{
    int t = blockIdx.x;
    int lane = threadIdx.x & 31, w = threadIdx.x >> 5;
    float4 v = ((const float4*)(in + (size_t)t*DIM))[threadIdx.x];
    float s = v.x + v.y + v.z + v.w;
    float q = v.x*v.x + v.y*v.y + v.z*v.z + v.w*v.w;
    #pragma unroll
    for (int o = 16; o; o >>= 1) {
        s += __shfl_xor_sync(0xffffffffu, s, o);
        q += __shfl_xor_sync(0xffffffffu, q, o);
    }
    __shared__ float ss[4], qq[4];
    if (lane == 0) { ss[w] = s; qq[w] = q; }
    __syncthreads();
    s = ss[0] + ss[1] + ss[2] + ss[3];
    q = qq[0] + qq[1] + qq[2] + qq[3];
    float mean = s * (1.0f / DIM);
    float var  = q * (1.0f / DIM) - mean * mean;
    float inv  = rsqrtf(var + 1e-5f);
    float4 gg = ((const float4*)g)[threadIdx.x];
    float4 bb = ((const float4*)b)[threadIdx.x];
    float o0 = (v.x - mean) * inv * gg.x + bb.x;
    float o1 = (v.y - mean) * inv * gg.y + bb.y;
    float o2 = (v.z - mean) * inv * gg.z + bb.z;
    float o3 = (v.w - mean) * inv * gg.w + bb.w;
    __nv_bfloat162* op = (__nv_bfloat162*)(out + (size_t)t*DIM) + 2*threadIdx.x;
    op[0] = __floats2bfloat162_rn(o0, o1);
    op[1] = __floats2bfloat162_rn(o2, o3);
}

// ---------------- bf16 tensor-core GEMM (cp.async 4-stage pipeline) -------
// C[M,N] = A[M,K] @ B[K,N] (+ epilogue).
// Smem layouts and fragment path identical to the proven round-7 kernel;
// only the GMEM->SMEM staging changed: 4-stage cp.async, wait_group 2
// (two full iterations of latency cover), no register staging, no STS
// on the warp critical path.
#define EPI_NONE 0
#define EPI_BIAS 1
#define EPI_GELU 2
#define EPI_SIG  3
#define EPI_RES  4

#define ASTR 20            // A row stride (uint32)
#define BSTR 136           // B row stride (uint32)
#define GST  4             // pipeline stages
#define ASZ  (128*ASTR)    // 2560 u32 per A stage
#define BSZ  (16*BSTR)     // 2176 u32 per B stage
#define STGU (ASZ+BSZ)     // 4736 u32 per stage
#define GSMEM (GST*STGU*4) // 75776 bytes dynamic smem

template<int EPI, int OBF>
__global__ __launch_bounds__(256, 2)
void bgemm_k(const __nv_bfloat16* __restrict__ Abf, const uint32_t* __restrict__ Bp,
             void* __restrict__ Cout, int M, int N, int K,
             const float* __restrict__ bias, const float* __restrict__ res)
{
    extern __shared__ __align__(16) uint32_t dsm[];

    const uint32_t* A32 = (const uint32_t*)Abf;
    const int K2 = K >> 1;

    const int tid   = threadIdx.x;
    const int warp  = tid >> 5, lane = tid & 31;
    const int group = lane >> 2, tig = lane & 3;
    const int wm = (warp >> 2) * 64;
    const int wn = (warp & 3) * 32;
    const int m0 = blockIdx.y * 128, n0 = blockIdx.x * 128;

    // per-thread staging coordinates (same mapping as proven kernel)
    const int rowA0 = tid >> 2,        p4 = (tid & 3) * 4;          // ld 0
    const int rowA1 = (256 + tid) >> 2;                              // ld 1 (p4 same)
    const int pB0 = (tid >> 3) & 15,   cB0 = ((tid & 7) | ((tid >> 7) << 3)) * 4;
    const int pB1 = ((256 + tid) >> 3) & 15,
              cB1 = (((256 + tid) & 7) | (((256 + tid) >> 7) << 3)) * 4;

    const uint32_t sbase = smem_u32(dsm);

    auto stage_cp = [&](int kt, int s) {
        uint32_t ab = sbase + (uint32_t)(s * STGU) * 4u;
        uint32_t bb = ab + ASZ * 4u;
        cp16(ab + (uint32_t)(rowA0 * ASTR + p4) * 4u,
             A32 + (size_t)(m0 + rowA0) * K2 + kt * 16 + p4);
        cp16(ab + (uint32_t)(rowA1 * ASTR + p4) * 4u,
             A32 + (size_t)(m0 + rowA1) * K2 + kt * 16 + p4);
        cp16(bb + (uint32_t)(pB0 * BSTR + cB0) * 4u,
             Bp + (size_t)(kt * 16 + pB0) * N + n0 + cB0);
        cp16(bb + (uint32_t)(pB1 * BSTR + cB1) * 4u,
             Bp + (size_t)(kt * 16 + pB1) * N + n0 + cB1);
        cp_commit();
    };

    const int nk = K / 32;   // >= 4 for all shapes here (K >= 128)

    stage_cp(0, 0);
    stage_cp(1, 1);
    stage_cp(2, 2);
    cp_wait<2>();            // stage 0 complete
    __syncthreads();

    float acc[4][4][4];
    #pragma unroll
    for (int mi = 0; mi < 4; mi++)
        #pragma unroll
        for (int ni = 0; ni < 4; ni++)
            #pragma unroll
            for (int r = 0; r < 4; r++) acc[mi][ni][r] = 0.f;

    for (int kt = 0; kt < nk; kt++) {
        const int buf = kt & 3;
        // fill stage kt+3 (its buffer's readers finished at end of iter kt-1)
        if (kt + 3 < nk) stage_cp(kt + 3, (kt + 3) & 3);
        else             cp_commit();   // keep group accounting uniform

        const uint32_t* As_ = dsm + buf * STGU;
        const uint32_t* Bs_ = As_ + ASZ;

        #pragma unroll
        for (int k16 = 0; k16 < 2; k16++) {
            const int kr0 = k16 * 8 + tig, kr1 = kr0 + 4;
            uint32_t a[4][4], b[4][2];
            #pragma unroll
            for (int mi = 0; mi < 4; mi++) {
                int mm = wm + mi * 16 + group;
                a[mi][0] = As_[mm * ASTR + kr0];
                a[mi][1] = As_[(mm + 8) * ASTR + kr0];
                a[mi][2] = As_[mm * ASTR + kr1];
                a[mi][3] = As_[(mm + 8) * ASTR + kr1];
            }
            #pragma unroll
            for (int ni = 0; ni < 4; ni++) {
                int nn = wn + ni * 8 + group;
                b[ni][0] = Bs_[kr0 * BSTR + nn];
                b[ni][1] = Bs_[kr1 * BSTR + nn];
            }
            #pragma unroll
            for (int mi = 0; mi < 4; mi++)
                #pragma unroll
                for (int ni = 0; ni < 4; ni++) {
                    asm volatile(
                        "mma.sync.aligned.m16n8k16.row.col.f32.bf16.bf16.f32 "
                        "{%0,%1,%2,%3}, {%4,%5,%6,%7}, {%8,%9}, {%0,%1,%2,%3};"
                        : "+f"(acc[mi][ni][0]), "+f"(acc[mi][ni][1]),
                          "+f"(acc[mi][ni][2]), "+f"(acc[mi][ni][3])
                        : "r"(a[mi][0]), "r"(a[mi][1]), "r"(a[mi][2]), "r"(a[mi][3]),
                          "r"(b[ni][0]), "r"(b[ni][1]));
                }
        }

        cp_wait<2>();        // stage kt+1 complete (2 iterations of cover)
        __syncthreads();
    }

    // epilogue (unchanged)
    #pragma unroll
    for (int mi = 0; mi < 4; mi++) {
        #pragma unroll
        for (int half = 0; half < 2; half++) {
            int m = m0 + wm + mi * 16 + group + half * 8;
            #pragma unroll
            for (int ni = 0; ni < 4; ni++) {
                int n = n0 + wn + ni * 8 + tig * 2;
                float v0 = acc[mi][ni][half * 2 + 0];
                float v1 = acc[mi][ni][half * 2 + 1];
                if (EPI != EPI_NONE) { v0 += bias[n]; v1 += bias[n + 1]; }
                if (EPI == EPI_GELU) {
                    v0 = 0.5f * v0 * (1.0f + erff(v0 * 0.70710678118654752f));
                    v1 = 0.5f * v1 * (1.0f + erff(v1 * 0.70710678118654752f));
                } else if (EPI == EPI_SIG) {
                    v0 = 1.0f / (1.0f + __expf(-v0));
                    v1 = 1.0f / (1.0f + __expf(-v1));
                } else if (EPI == EPI_RES) {
                    v0 += res[(size_t)m * N + n];
                    v1 += res[(size_t)m * N + n + 1];
                }
                if (OBF) {
                    __nv_bfloat162 h2 = __floats2bfloat162_rn(v0, v1);
                    *(__nv_bfloat162*)((__nv_bfloat16*)Cout + (size_t)m * N + n) = h2;
                } else {
                    *(float2*)((float*)Cout + (size_t)m * N + n) = make_float2(v0, v1);
                }
            }
        }
    }
}

// ---------------- flash attention (tensor cores, proven round-14) ---------
#define AQ_OFF 0
#define AK_OFF 32768
#define AV_OFF 65536
#define ATT2_SMEM (96*1024)

__global__ __launch_bounds__(256)
void attn2_k(const __nv_bfloat16* __restrict__ qkv, __nv_bfloat16* __restrict__ out)
{
    extern __shared__ __align__(1024) uint8_t sm8[];
    const uint32_t sb = smem_u32(sm8);
    const int tid = threadIdx.x;
    const int h = blockIdx.x & 7, bp = blockIdx.x >> 3;
    const int tbase = bp * NN, hoff = h * DHEAD;

    for (int idx = tid; idx < 2048; idx += 256) {
        int r = idx >> 3, u = idx & 7;
        int q = u >> 2, c = u & 3;
        const __nv_bfloat16* rowp = qkv + (size_t)(tbase + r) * 1536;
        *(uint4*)(sm8 + AQ_OFF + q * 16384 + tile_off(r, c)) =
            *(const uint4*)(rowp + hoff + q * 32 + c * 8);
        *(uint4*)(sm8 + AK_OFF + q * 16384 + tile_off(r, c)) =
            *(const uint4*)(rowp + 512 + hoff + q * 32 + c * 8);
    }
    for (int idx = tid; idx < 2048; idx += 256) {
        int r = idx >> 3, u = idx & 7;
        uint4 v = *(const uint4*)(qkv + (size_t)(tbase + r) * 1536 + 1024 + hoff + u * 8);
        const __nv_bfloat16* pv = (const __nv_bfloat16*)&v;
        int chunk = r >> 5, col = r & 31, cc = col >> 3, wi = col & 7;
        #pragma unroll
        for (int j = 0; j < 8; j++) {
            int d = u * 8 + j;
            uint32_t a = AV_OFF + chunk * 4096 + (d >> 1) * 128
                       + (((4 * (d & 1) + cc) ^ ((d >> 1) & 7)) * 16) + wi * 2;
            *(__nv_bfloat16*)(sm8 + a) = pv[j];
        }
    }
    __syncthreads();

    const int warp = tid >> 5, lane = tid & 31;
    const int g = lane >> 2, t4 = lane & 3;
    const int R = warp * 32;
    const int laneA = (lane & 7) + ((lane >> 3) & 1) * 8;
    const int cA    = (lane >> 4) & 1;
    const int laneB = (lane & 7) + ((lane >> 4) & 1) * 8;
    const int cBi   = (lane >> 3) & 1;

    float mrow[2][2], lrow[2][2];
    float o[2][8][4];
    #pragma unroll
    for (int mi = 0; mi < 2; mi++)
        #pragma unroll
        for (int hf = 0; hf < 2; hf++) { mrow[mi][hf] = -1e30f; lrow[mi][hf] = 0.f; }
    #pragma unroll
    for (int mi = 0; mi < 2; mi++)
        #pragma unroll
        for (int ni = 0; ni < 8; ni++)
            #pragma unroll
            for (int r = 0; r < 4; r++) o[mi][ni][r] = 0.f;

    for (int blk = 0; blk < 4; blk++) {
        float s[2][8][4];
        #pragma unroll
        for (int mi = 0; mi < 2; mi++)
            #pragma unroll
            for (int ni = 0; ni < 8; ni++)
                #pragma unroll
                for (int r = 0; r < 4; r++) s[mi][ni][r] = 0.f;

        #pragma unroll
        for (int st = 0; st < 4; st++) {
            const int q = st >> 1;
            const uint32_t ko = (uint32_t)((st & 1) * 32);
            uint32_t a[2][4], bk[8][2];
            #pragma unroll
            for (int mi = 0; mi < 2; mi++) {
                uint32_t ad = (sb + AQ_OFF + q * 16384 + tile_off(R + mi * 16 + laneA, cA)) ^ ko;
                asm volatile(
                    "ldmatrix.sync.aligned.m8n8.x4.shared.b16 {%0,%1,%2,%3}, [%4];"
                    : "=r"(a[mi][0]), "=r"(a[mi][1]), "=r"(a[mi][2]), "=r"(a[mi][3])
                    : "r"(ad));
            }
            #pragma unroll
            for (int p = 0; p < 4; p++) {
                uint32_t ad = (sb + AK_OFF + q * 16384 + tile_off(blk * 64 + p * 16 + laneB, cBi)) ^ ko;
                asm volatile(
                    "ldmatrix.sync.aligned.m8n8.x4.shared.b16 {%0,%1,%2,%3}, [%4];"
                    : "=r"(bk[2*p][0]), "=r"(bk[2*p][1]), "=r"(bk[2*p+1][0]), "=r"(bk[2*p+1][1])
                    : "r"(ad));
            }
            #pragma unroll
            for (int mi = 0; mi < 2; mi++)
                #pragma unroll
                for (int ni = 0; ni < 8; ni++) {
                    asm volatile(
                        "mma.sync.aligned.m16n8k16.row.col.f32.bf16.bf16.f32 "
                        "{%0,%1,%2,%3}, {%4,%5,%6,%7}, {%8,%9}, {%0,%1,%2,%3};"
                        : "+f"(s[mi][ni][0]), "+f"(s[mi][ni][1]),
                          "+f"(s[mi][ni][2]), "+f"(s[mi][ni][3])
                        : "r"(a[mi][0]), "r"(a[mi][1]), "r"(a[mi][2]), "r"(a[mi][3]),
                          "r"(bk[ni][0]), "r"(bk[ni][1]));
                }
        }

        #pragma unroll
        for (int mi = 0; mi < 2; mi++)
            #pragma unroll
            for (int ni = 0; ni < 8; ni++)
                #pragma unroll
                for (int r = 0; r < 4; r++) s[mi][ni][r] *= 0.125f;

        #pragma unroll
        for (int mi = 0; mi < 2; mi++) {
            #pragma unroll
            for (int hf = 0; hf < 2; hf++) {
                float bm = -1e30f;
                #pragma unroll
                for (int ni = 0; ni < 8; ni++) {
                    bm = fmaxf(bm, s[mi][ni][hf*2]);
                    bm = fmaxf(bm, s[mi][ni][hf*2+1]);
                }
                bm = fmaxf(bm, __shfl_xor_sync(0xffffffffu, bm, 1));
                bm = fmaxf(bm, __shfl_xor_sync(0xffffffffu, bm, 2));
                float mnew = fmaxf(mrow[mi][hf], bm);
                float corr = __expf(mrow[mi][hf] - mnew);
                mrow[mi][hf] = mnew;
                float rs = 0.f;
                #pragma unroll
                for (int ni = 0; ni < 8; ni++) {
                    float e0 = __expf(s[mi][ni][hf*2]   - mnew);
                    float e1 = __expf(s[mi][ni][hf*2+1] - mnew);
                    s[mi][ni][hf*2]   = e0;
                    s[mi][ni][hf*2+1] = e1;
                    rs += e0 + e1;
                }
                rs += __shfl_xor_sync(0xffffffffu, rs, 1);
                rs += __shfl_xor_sync(0xffffffffu, rs, 2);
                lrow[mi][hf] = lrow[mi][hf] * corr + rs;
                #pragma unroll
                for (int ni = 0; ni < 8; ni++) {
                    o[mi][ni][hf*2]   *= corr;
                    o[mi][ni][hf*2+1] *= corr;
                }
            }
        }

        uint32_t pa[2][4][4];
        #pragma unroll
        for (int mi = 0; mi < 2; mi++)
            #pragma unroll
            for (int st = 0; st < 4; st++) {
                pa[mi][st][0] = packbf(s[mi][2*st][0],   s[mi][2*st][1]);
                pa[mi][st][1] = packbf(s[mi][2*st][2],   s[mi][2*st][3]);
                pa[mi][st][2] = packbf(s[mi][2*st+1][0], s[mi][2*st+1][1]);
                pa[mi][st][3] = packbf(s[mi][2*st+1][2], s[mi][2*st+1][3]);
            }

        #pragma unroll
        for (int st = 0; st < 4; st++) {
            const int vc = blk * 2 + (st >> 1);
            const uint32_t ko = (uint32_t)((st & 1) * 32);
            uint32_t vb[8][2];
            #pragma unroll
            for (int pd = 0; pd < 4; pd++) {
                uint32_t ad = (sb + AV_OFF + vc * 4096 + tile_off(pd * 16 + laneB, cBi)) ^ ko;
                asm volatile(
                    "ldmatrix.sync.aligned.m8n8.x4.shared.b16 {%0,%1,%2,%3}, [%4];"
                    : "=r"(vb[2*pd][0]), "=r"(vb[2*pd][1]), "=r"(vb[2*pd+1][0]), "=r"(vb[2*pd+1][1])
                    : "r"(ad));
            }
            #pragma unroll
            for (int mi = 0; mi < 2; mi++)
                #pragma unroll
                for (int di = 0; di < 8; di++) {
                    asm volatile(
                        "mma.sync.aligned.m16n8k16.row.col.f32.bf16.bf16.f32 "
                        "{%0,%1,%2,%3}, {%4,%5,%6,%7}, {%8,%9}, {%0,%1,%2,%3};"
                        : "+f"(o[mi][di][0]), "+f"(o[mi][di][1]),
                          "+f"(o[mi][di][2]), "+f"(o[mi][di][3])
                        : "r"(pa[mi][st][0]), "r"(pa[mi][st][1]),
                          "r"(pa[mi][st][2]), "r"(pa[mi][st][3]),
                          "r"(vb[di][0]), "r"(vb[di][1]));
                }
        }
    }

    #pragma unroll
    for (int mi = 0; mi < 2; mi++) {
        #pragma unroll
        for (int hf = 0; hf < 2; hf++) {
            int row = tbase + R + mi * 16 + g + hf * 8;
            float inv = 1.0f / lrow[mi][hf];
            #pragma unroll
            for (int ni = 0; ni < 8; ni++) {
                __nv_bfloat162 h2 = __floats2bfloat162_rn(o[mi][ni][hf*2] * inv,
                                                          o[mi][ni][hf*2+1] * inv);
                *(__nv_bfloat162*)(out + (size_t)row * DIM + hoff + ni * 8 + t4 * 2) = h2;
            }
        }
    }
}

// ---------------- biattn pieces ----------------
__global__ void mean_k(const __nv_bfloat16* __restrict__ bx, __nv_bfloat16* __restrict__ xg)
{
    int idx = blockIdx.x * blockDim.x + threadIdx.x;
    if (idx >= BB * NN * DIM) return;
    int d = idx % DIM;
    int n = (idx / DIM) % NN;
    int b = idx / (DIM * NN);
    size_t base = ((size_t)(b * PP) * NN + n) * DIM + d;
    const size_t st = (size_t)NN * DIM;
    float s = __bfloat162float(bx[base]) + __bfloat162float(bx[base + st])
            + __bfloat162float(bx[base + 2*st]) + __bfloat162float(bx[base + 3*st]);
    xg[idx] = __float2bfloat16(0.25f * s);
}

__global__ __launch_bounds__(256)
void sattn_k(const __nv_bfloat16* __restrict__ xl, const __nv_bfloat16* __restrict__ xga,
             const float* __restrict__ ws, const float* __restrict__ bsc,
             float* __restrict__ sa)
{
    int gtid = blockIdx.x * 256 + threadIdx.x;
    int t = gtid >> 5;
    int lane = threadIdx.x & 31;
    if (t >= TT) return;
    int b = t / (PP * NN);
    int n = t % NN;
    const __nv_bfloat16* xlp = xl  + (size_t)t * RED;
    const __nv_bfloat16* xgp = xga + ((size_t)b * NN + n) * RED;
    float s = 0.f;
    for (int i = lane; i < RED; i += 32)
        s += __bfloat162float(xlp[i]) * ws[i] + __bfloat162float(xgp[i]) * ws[RED + i];
    #pragma unroll
    for (int o = 16; o; o >>= 1) s += __shfl_xor_sync(0xffffffffu, s, o);
    if (lane == 0) sa[t] = 1.0f / (1.0f + __expf(-(s + bsc[0])));
}

__global__ void fuse_k(const float* __restrict__ h, const float* __restrict__ ca,
                       const float* __restrict__ sa, const float* __restrict__ x,
                       float* __restrict__ out)
{
    int idx = blockIdx.x * blockDim.x + threadIdx.x;
    if (idx >= TT * DIM) return;
    int t = idx / DIM;
    int d = idx % DIM;
    int b = t / (PP * NN);
    int n = t % NN;
    out[idx] = x[idx] + h[idx] * ca[((size_t)b * NN + n) * DIM + d] * sa[t];
}

// ---------------- host driver ----------------
extern "C" void kernel_launch(void* const* d_in, const int* in_sizes, int n_in,
                              void* d_out, int out_size)
{
    const float* x_in  = (const float*)d_in[0];
    const float* ln1_g = (const float*)d_in[1];
    const float* ln1_b = (const float*)d_in[2];
    const float* w_qkv = (const float*)d_in[3];
    const float* w_o   = (const float*)d_in[4];
    const float* b_o   = (const float*)d_in[5];
    const float* ln2_g = (const float*)d_in[6];
    const float* ln2_b = (const float*)d_in[7];
    const float* w1    = (const float*)d_in[8];
    const float* b1    = (const float*)d_in[9];
    const float* w2    = (const float*)d_in[10];
    const float* b2    = (const float*)d_in[11];
    const float* bn_g  = (const float*)d_in[12];
    const float* bn_b  = (const float*)d_in[13];
    const float* wg    = (const float*)d_in[14];
    const float* bg    = (const float*)d_in[15];
    const float* wl    = (const float*)d_in[16];
    const float* bl    = (const float*)d_in[17];
    const float* wc    = (const float*)d_in[18];
    const float* bc    = (const float*)d_in[19];
    const float* ws    = (const float*)d_in[20];
    const float* bs    = (const float*)d_in[21];

    float* base = nullptr;
    cudaGetSymbolAddress((void**)&base, g_scratch);
    float*          X   = base + OFF_X;
    __nv_bfloat16*  Y   = (__nv_bfloat16*)(base + OFF_Y);
    __nv_bfloat16*  QKV = (__nv_bfloat16*)(base + OFF_QKV);
    __nv_bfloat16*  ATT = (__nv_bfloat16*)(base + OFF_ATT);
    __nv_bfloat16*  H1  = (__nv_bfloat16*)(base + OFF_H1);
    float*          H   = base + OFF_H;
    __nv_bfloat16*  BX  = (__nv_bfloat16*)(base + OFF_BX);
    __nv_bfloat16*  XG  = (__nv_bfloat16*)(base + OFF_XG);
    __nv_bfloat16*  XGA = (__nv_bfloat16*)(base + OFF_XGA);
    __nv_bfloat16*  XL  = (__nv_bfloat16*)(base + OFF_XL);
    float*          CA  = base + OFF_CA;
    float*          SA  = base + OFF_SA;
    uint32_t*       WP  = (uint32_t*)(base + OFF_WP);

    cudaFuncSetAttribute((const void*)attn2_k,
                         cudaFuncAttributeMaxDynamicSharedMemorySize, ATT2_SMEM);
    cudaFuncSetAttribute((const void*)bgemm_k<EPI_NONE,1>,
                         cudaFuncAttributeMaxDynamicSharedMemorySize, GSMEM);
    cudaFuncSetAttribute((const void*)bgemm_k<EPI_RES,0>,
                         cudaFuncAttributeMaxDynamicSharedMemorySize, GSMEM);
    cudaFuncSetAttribute((const void*)bgemm_k<EPI_GELU,1>,
                         cudaFuncAttributeMaxDynamicSharedMemorySize, GSMEM);
    cudaFuncSetAttribute((const void*)bgemm_k<EPI_BIAS,0>,
                         cudaFuncAttributeMaxDynamicSharedMemorySize, GSMEM);
    cudaFuncSetAttribute((const void*)bgemm_k<EPI_SIG,0>,
                         cudaFuncAttributeMaxDynamicSharedMemorySize, GSMEM);

    const int EW = 256;

    // pack all weights to bf16x2 pair layout (once per launch, ~30us)
    {
        int t;
        t = 4*256*1536; packw_k<<<(t+EW-1)/EW, EW>>>(w_qkv, WP+WP_QKV,  512, 1536, t);
        t = 4*256*512;  packw_k<<<(t+EW-1)/EW, EW>>>(w_o,   WP+WP_O,    512,  512, t);
        t = 4*256*2048; packw_k<<<(t+EW-1)/EW, EW>>>(w1,    WP+WP_W1,   512, 2048, t);
        t = 4*1024*512; packw_k<<<(t+EW-1)/EW, EW>>>(w2,    WP+WP_W2,  2048,  512, t);
        t = 4*256*128;  packw_k<<<(t+EW-1)/EW, EW>>>(wg,    WP+WP_WG,   512,  128, t);
        t = 4*256*128;  packw_k<<<(t+EW-1)/EW, EW>>>(wl,    WP+WP_WL,   512,  128, t);
        t = 4*64*512;   packw_k<<<(t+EW-1)/EW, EW>>>(wc,    WP+WP_WC,   128,  512, t);
    }

    for (int l = 0; l < DEPTH; l++) {
        const float* Xin = (l == 0) ? x_in : X;

        // ---- attention half ----
        ln_k<<<TT, 128>>>(Xin, Y, ln1_g + l*DIM, ln1_b + l*DIM);
        bgemm_k<EPI_NONE,1><<<dim3(3*DIM/128, TT/128), 256, GSMEM>>>(
            Y, WP + WP_QKV + (size_t)l*256*1536, QKV, TT, 3*DIM, DIM, nullptr, nullptr);
        attn2_k<<<BB*PP*HEADS, 256, ATT2_SMEM>>>(QKV, ATT);
        bgemm_k<EPI_RES,0><<<dim3(DIM/128, TT/128), 256, GSMEM>>>(
            ATT, WP + WP_O + (size_t)l*256*512, X, TT, DIM, DIM, b_o + l*DIM, Xin);

        // ---- mlp half ----
        ln_k<<<TT, 128>>>(X, Y, ln2_g + l*DIM, ln2_b + l*DIM);
        bgemm_k<EPI_GELU,1><<<dim3(MLPD/128, TT/128), 256, GSMEM>>>(
            Y, WP + WP_W1 + (size_t)l*256*2048, H1, TT, MLPD, DIM, b1 + l*MLPD, nullptr);
        bgemm_k<EPI_BIAS,0><<<dim3(DIM/128, TT/128), 256, GSMEM>>>(
            H1, WP + WP_W2 + (size_t)l*1024*512, H, TT, DIM, MLPD, b2 + l*DIM, nullptr);

        // ---- biattn ----
        ln_k<<<TT, 128>>>(H, BX, bn_g + l*DIM, bn_b + l*DIM);
        mean_k<<<(BB*NN*DIM + EW - 1) / EW, EW>>>(BX, XG);
        bgemm_k<EPI_GELU,1><<<dim3(RED/128, BB*NN/128), 256, GSMEM>>>(
            XG, WP + WP_WG + (size_t)l*256*128, XGA, BB*NN, RED, DIM, bg + l*RED, nullptr);
        bgemm_k<EPI_GELU,1><<<dim3(RED/128, TT/128), 256, GSMEM>>>(
            BX, WP + WP_WL + (size_t)l*256*128, XL, TT, RED, DIM, bl + l*RED, nullptr);
        bgemm_k<EPI_SIG,0><<<dim3(DIM/128, BB*NN/128), 256, GSMEM>>>(
            XGA, WP + WP_WC + (size_t)l*64*512, CA, BB*NN, DIM, RED, bc + l*DIM, nullptr);
        sattn_k<<<(TT*32 + 255) / 256, 256>>>(XL, XGA, ws + l*2*RED, bs + l, SA);

        float* fuse_out = (l == DEPTH - 1) ? (float*)d_out : X;
        fuse_k<<<(TT*DIM + EW - 1) / EW, EW>>>(H, CA, SA, X, fuse_out);
    }
}

// round 16
// speedup vs baseline: 2.7598x; 1.1224x over previous
#include <cuda_runtime.h>
#include <cuda_bf16.h>
#include <cstdint>

// ---------------- problem constants ----------------
#define DEPTH  4
#define HEADS  8
#define DHEAD  64
#define DIM    512
#define MLPD   2048
#define RED    128
#define BB     8
#define PP     4
#define NN     256
#define TT     (BB*PP*NN)     // 8192 tokens

// ---------------- scratch ----------------
static const size_t OFF_X   = 0;                               // f32 residual
static const size_t OFF_Y   = OFF_X   + (size_t)TT*DIM;        // bf16 LN out
static const size_t OFF_QKV = OFF_Y   + (size_t)TT*DIM;        // bf16
static const size_t OFF_ATT = OFF_QKV + (size_t)TT*3*DIM;      // bf16
static const size_t OFF_H1  = OFF_ATT + (size_t)TT*DIM;        // bf16
static const size_t OFF_H   = OFF_H1  + (size_t)TT*MLPD;       // f32
static const size_t OFF_BX  = OFF_H   + (size_t)TT*DIM;        // bf16
static const size_t OFF_XG  = OFF_BX  + (size_t)TT*DIM;        // bf16
static const size_t OFF_XGA = OFF_XG  + (size_t)BB*NN*DIM;     // bf16
static const size_t OFF_XL  = OFF_XGA + (size_t)BB*NN*RED;     // bf16
static const size_t OFF_CA  = OFF_XL  + (size_t)TT*RED;        // f32
static const size_t OFF_SA  = OFF_CA  + (size_t)BB*NN*DIM;     // f32
static const size_t OFF_WT  = OFF_SA  + TT;                    // transposed bf16 weights

// transposed-weight sub-offsets (bf16 element units): layout [d][n][k]
static const size_t WT_QKV = 0;
static const size_t WT_O   = WT_QKV + (size_t)4*1536*512;
static const size_t WT_W1  = WT_O   + (size_t)4*512*512;
static const size_t WT_W2  = WT_W1  + (size_t)4*2048*512;
static const size_t WT_WG  = WT_W2  + (size_t)4*512*2048;
static const size_t WT_WL  = WT_WG  + (size_t)4*128*512;
static const size_t WT_WC  = WT_WL  + (size_t)4*128*512;
static const size_t WT_TOT = WT_WC  + (size_t)4*512*128;

static const size_t SCRATCH_FLOATS = OFF_WT + (WT_TOT + 1) / 2;

__device__ float g_scratch[SCRATCH_FLOATS];

// ---------------- helpers ----------------
__device__ __forceinline__ uint32_t smem_u32(const void* p) {
    uint32_t a;
    asm("{ .reg .u64 t; cvta.to.shared.u64 t, %1; cvt.u32.u64 %0, t; }" : "=r"(a) : "l"(p));
    return a;
}
__device__ __forceinline__ void cp16(uint32_t dst, const void* src) {
    asm volatile("cp.async.cg.shared.global [%0], [%1], 16;\n" :: "r"(dst), "l"(src));
}
__device__ __forceinline__ void cp_commit() {
    asm volatile("cp.async.commit_group;\n");
}
template<int N>
__device__ __forceinline__ void cp_wait() {
    asm volatile("cp.async.wait_group %0;\n" :: "n"(N));
}
__device__ __forceinline__ uint32_t packbf(float x, float y) {
    __nv_bfloat162 h = __floats2bfloat162_rn(x, y);
    return *reinterpret_cast<uint32_t*>(&h);
}
// verified swizzled tile layout: row r, 16B chunk c (0..3), 64B per row
// k16 sub-step (c -> c+2) on the swizzled address is addr ^ 32 (NOT +32).
__device__ __forceinline__ uint32_t tile_off(int r, int c) {
    return (uint32_t)((r >> 1) * 128 + (((4 * (r & 1) + c) ^ ((r >> 1) & 7)) * 16));
}

// tiled transpose-pack: W[d][K][N] f32 -> Wt[d][N][K] bf16  (proven round 10)
__global__ void packwt_k(const float* __restrict__ W, __nv_bfloat16* __restrict__ Wt,
                         int K, int N)
{
    __shared__ float t[32][33];
    int k0 = blockIdx.x * 32, n0 = blockIdx.y * 32, d = blockIdx.z;
    const float* Wd = W + (size_t)d * K * N;
    #pragma unroll
    for (int i = 0; i < 32; i += 8)
        t[threadIdx.y + i][threadIdx.x] =
            Wd[(size_t)(k0 + threadIdx.y + i) * N + n0 + threadIdx.x];
    __syncthreads();
    __nv_bfloat16* out = Wt + (size_t)d * N * K;
    #pragma unroll
    for (int i = 0; i < 32; i += 8)
        out[(size_t)(n0 + threadIdx.y + i) * K + k0 + threadIdx.x] =
            __float2bfloat16(t[threadIdx.x][threadIdx.y + i]);
}

// ---------------- layernorm: fp32 in, bf16 out ----------------
__global__ __launch_bounds__(128)
void ln_k(const float* __restrict__ in, __nv_bfloat16* __restrict__ out,
          const float* __restrict__ g, const float* __restrict__ b)
{
    int t = blockIdx.x;
    int lane = threadIdx.x & 31, w = threadIdx.x >> 5;
    float4 v = ((const float4*)(in + (size_t)t*DIM))[threadIdx.x];
    float s = v.x + v.y + v.z + v.w;
    float q = v.x*v.x + v.y*v.y + v.z*v.z + v.w*v.w;
    #pragma unroll
    for (int o = 16; o; o >>= 1) {
        s += __shfl_xor_sync(0xffffffffu, s, o);
        q += __shfl_xor_sync(0xffffffffu, q, o);
    }
    __shared__ float ss[4], qq[4];
    if (lane == 0) { ss[w] = s; qq[w] = q; }
    __syncthreads();
    s = ss[0] + ss[1] + ss[2] + ss[3];
    q = qq[0] + qq[1] + qq[2] + qq[3];
    float mean = s * (1.0f / DIM);
    float var  = q * (1.0f / DIM) - mean * mean;
    float inv  = rsqrtf(var + 1e-5f);
    float4 gg = ((const float4*)g)[threadIdx.x];
    float4 bb = ((const float4*)b)[threadIdx.x];
    float o0 = (v.x - mean) * inv * gg.x + bb.x;
    float o1 = (v.y - mean) * inv * gg.y + bb.y;
    float o2 = (v.z - mean) * inv * gg.z + bb.z;
    float o3 = (v.w - mean) * inv * gg.w + bb.w;
    __nv_bfloat162* op = (__nv_bfloat162*)(out + (size_t)t*DIM) + 2*threadIdx.x;
    op[0] = __floats2bfloat162_rn(o0, o1);
    op[1] = __floats2bfloat162_rn(o2, o3);
}

// ---------------- bf16 GEMM: ldmatrix fragments + 4-stage cp.async --------
// C[M,N] = A[M,K] @ Bt[N,K]^T (+ epilogue). A bf16 row-major, Bt bf16 [N][K].
// BM=BN=128, BK=32, 8 warps 2x4, warp tile 64x32.
// Both components individually proven: tile_off/ldmatrix/XOR path (rounds 10+14),
// 4-stage wait_group-2 cp.async pipeline (round 15).
#define EPI_NONE 0
#define EPI_BIAS 1
#define EPI_GELU 2
#define EPI_SIG  3
#define EPI_RES  4

#define GST    4
#define TILEB  8192
#define STAGEB (2*TILEB)
#define GSMEM  (GST*STAGEB)   // 65536 bytes dynamic smem

template<int EPI, int OBF>
__global__ __launch_bounds__(256, 2)
void bgemm_k(const __nv_bfloat16* __restrict__ Abf, const __nv_bfloat16* __restrict__ Bt,
             void* __restrict__ Cout, int M, int N, int K,
             const float* __restrict__ bias, const float* __restrict__ res)
{
    extern __shared__ __align__(1024) uint8_t dsm[];
    const uint32_t sbase = smem_u32(dsm);

    const int tid   = threadIdx.x;
    const int warp  = tid >> 5, lane = tid & 31;
    const int group = lane >> 2, tig = lane & 3;
    const int wm = (warp >> 2) * 64;
    const int wn = (warp & 3) * 32;
    const int m0 = blockIdx.y * 128, n0 = blockIdx.x * 128;

    // cp.async staging: thread handles 2 chunks of A and 2 of B per stage
    auto stage_cp = [&](int kt, int s) {
        #pragma unroll
        for (int i = 0; i < 2; i++) {
            int idx = i * 256 + tid;
            int r = idx >> 2, c = idx & 3;
            uint32_t o = tile_off(r, c);
            cp16(sbase + s * STAGEB + o,
                 Abf + (size_t)(m0 + r) * K + kt * 32 + c * 8);
            cp16(sbase + s * STAGEB + TILEB + o,
                 Bt + (size_t)(n0 + r) * K + kt * 32 + c * 8);
        }
        cp_commit();
    };

    // ldmatrix per-lane base addresses (verified mapping)
    const int rA = wm + (lane & 7) + ((lane >> 3) & 1) * 8;
    const int cA = (lane >> 4) & 1;
    const uint32_t aBase = sbase + tile_off(rA, cA);
    const int rB = wn + (lane & 7) + ((lane >> 4) & 1) * 8;
    const int cB = (lane >> 3) & 1;
    const uint32_t bBase = sbase + TILEB + tile_off(rB, cB);

    const int nk = K / 32;   // >= 4 for all shapes here

    stage_cp(0, 0);
    stage_cp(1, 1);
    stage_cp(2, 2);
    cp_wait<2>();
    __syncthreads();

    float acc[4][4][4];
    #pragma unroll
    for (int mi = 0; mi < 4; mi++)
        #pragma unroll
        for (int ni = 0; ni < 4; ni++)
            #pragma unroll
            for (int r = 0; r < 4; r++) acc[mi][ni][r] = 0.f;

    for (int kt = 0; kt < nk; kt++) {
        const int buf = kt & 3;
        const uint32_t abuf = aBase + buf * STAGEB;
        const uint32_t bbuf = bBase + buf * STAGEB;

        if (kt + 3 < nk) stage_cp(kt + 3, (kt + 3) & 3);
        else             cp_commit();   // uniform group accounting

        #pragma unroll
        for (int k16 = 0; k16 < 2; k16++) {
            const uint32_t koff = k16 ? 32u : 0u;   // XOR step (swizzle-aware)
            uint32_t a[4][4], b[4][2];
            #pragma unroll
            for (int mi = 0; mi < 4; mi++) {
                asm volatile(
                    "ldmatrix.sync.aligned.m8n8.x4.shared.b16 {%0,%1,%2,%3}, [%4];"
                    : "=r"(a[mi][0]), "=r"(a[mi][1]), "=r"(a[mi][2]), "=r"(a[mi][3])
                    : "r"((abuf + mi * 1024u) ^ koff));
            }
            #pragma unroll
            for (int p = 0; p < 2; p++) {
                asm volatile(
                    "ldmatrix.sync.aligned.m8n8.x4.shared.b16 {%0,%1,%2,%3}, [%4];"
                    : "=r"(b[2*p][0]), "=r"(b[2*p][1]), "=r"(b[2*p+1][0]), "=r"(b[2*p+1][1])
                    : "r"((bbuf + p * 1024u) ^ koff));
            }
            #pragma unroll
            for (int mi = 0; mi < 4; mi++)
                #pragma unroll
                for (int ni = 0; ni < 4; ni++) {
                    asm volatile(
                        "mma.sync.aligned.m16n8k16.row.col.f32.bf16.bf16.f32 "
                        "{%0,%1,%2,%3}, {%4,%5,%6,%7}, {%8,%9}, {%0,%1,%2,%3};"
                        : "+f"(acc[mi][ni][0]), "+f"(acc[mi][ni][1]),
                          "+f"(acc[mi][ni][2]), "+f"(acc[mi][ni][3])
                        : "r"(a[mi][0]), "r"(a[mi][1]), "r"(a[mi][2]), "r"(a[mi][3]),
                          "r"(b[ni][0]), "r"(b[ni][1]));
                }
        }

        cp_wait<2>();        // next stage complete (2 iterations of cover)
        __syncthreads();     // all warps done with buf before overwrite
    }

    // epilogue
    #pragma unroll
    for (int mi = 0; mi < 4; mi++) {
        #pragma unroll
        for (int half = 0; half < 2; half++) {
            int m = m0 + wm + mi * 16 + group + half * 8;
            #pragma unroll
            for (int ni = 0; ni < 4; ni++) {
                int n = n0 + wn + ni * 8 + tig * 2;
                float v0 = acc[mi][ni][half * 2 + 0];
                float v1 = acc[mi][ni][half * 2 + 1];
                if (EPI != EPI_NONE) { v0 += bias[n]; v1 += bias[n + 1]; }
                if (EPI == EPI_GELU) {
                    v0 = 0.5f * v0 * (1.0f + erff(v0 * 0.70710678118654752f));
                    v1 = 0.5f * v1 * (1.0f + erff(v1 * 0.70710678118654752f));
                } else if (EPI == EPI_SIG) {
                    v0 = 1.0f / (1.0f + __expf(-v0));
                    v1 = 1.0f / (1.0f + __expf(-v1));
                } else if (EPI == EPI_RES) {
                    v0 += res[(size_t)m * N + n];
                    v1 += res[(size_t)m * N + n + 1];
                }
                if (OBF) {
                    __nv_bfloat162 h2 = __floats2bfloat162_rn(v0, v1);
                    *(__nv_bfloat162*)((__nv_bfloat16*)Cout + (size_t)m * N + n) = h2;
                } else {
                    *(float2*)((float*)Cout + (size_t)m * N + n) = make_float2(v0, v1);
                }
            }
        }
    }
}

// ---------------- flash attention (tensor cores, proven round-14) ---------
#define AQ_OFF 0
#define AK_OFF 32768
#define AV_OFF 65536
#define ATT2_SMEM (96*1024)

__global__ __launch_bounds__(256)
void attn2_k(const __nv_bfloat16* __restrict__ qkv, __nv_bfloat16* __restrict__ out)
{
    extern __shared__ __align__(1024) uint8_t sm8[];
    const uint32_t sb = smem_u32(sm8);
    const int tid = threadIdx.x;
    const int h = blockIdx.x & 7, bp = blockIdx.x >> 3;
    const int tbase = bp * NN, hoff = h * DHEAD;

    for (int idx = tid; idx < 2048; idx += 256) {
        int r = idx >> 3, u = idx & 7;
        int q = u >> 2, c = u & 3;
        const __nv_bfloat16* rowp = qkv + (size_t)(tbase + r) * 1536;
        *(uint4*)(sm8 + AQ_OFF + q * 16384 + tile_off(r, c)) =
            *(const uint4*)(rowp + hoff + q * 32 + c * 8);
        *(uint4*)(sm8 + AK_OFF + q * 16384 + tile_off(r, c)) =
            *(const uint4*)(rowp + 512 + hoff + q * 32 + c * 8);
    }
    for (int idx = tid; idx < 2048; idx += 256) {
        int r = idx >> 3, u = idx & 7;
        uint4 v = *(const uint4*)(qkv + (size_t)(tbase + r) * 1536 + 1024 + hoff + u * 8);
        const __nv_bfloat16* pv = (const __nv_bfloat16*)&v;
        int chunk = r >> 5, col = r & 31, cc = col >> 3, wi = col & 7;
        #pragma unroll
        for (int j = 0; j < 8; j++) {
            int d = u * 8 + j;
            uint32_t a = AV_OFF + chunk * 4096 + (d >> 1) * 128
                       + (((4 * (d & 1) + cc) ^ ((d >> 1) & 7)) * 16) + wi * 2;
            *(__nv_bfloat16*)(sm8 + a) = pv[j];
        }
    }
    __syncthreads();

    const int warp = tid >> 5, lane = tid & 31;
    const int g = lane >> 2, t4 = lane & 3;
    const int R = warp * 32;
    const int laneA = (lane & 7) + ((lane >> 3) & 1) * 8;
    const int cA    = (lane >> 4) & 1;
    const int laneB = (lane & 7) + ((lane >> 4) & 1) * 8;
    const int cBi   = (lane >> 3) & 1;

    float mrow[2][2], lrow[2][2];
    float o[2][8][4];
    #pragma unroll
    for (int mi = 0; mi < 2; mi++)
        #pragma unroll
        for (int hf = 0; hf < 2; hf++) { mrow[mi][hf] = -1e30f; lrow[mi][hf] = 0.f; }
    #pragma unroll
    for (int mi = 0; mi < 2; mi++)
        #pragma unroll
        for (int ni = 0; ni < 8; ni++)
            #pragma unroll
            for (int r = 0; r < 4; r++) o[mi][ni][r] = 0.f;

    for (int blk = 0; blk < 4; blk++) {
        float s[2][8][4];
        #pragma unroll
        for (int mi = 0; mi < 2; mi++)
            #pragma unroll
            for (int ni = 0; ni < 8; ni++)
                #pragma unroll
                for (int r = 0; r < 4; r++) s[mi][ni][r] = 0.f;

        #pragma unroll
        for (int st = 0; st < 4; st++) {
            const int q = st >> 1;
            const uint32_t ko = (uint32_t)((st & 1) * 32);
            uint32_t a[2][4], bk[8][2];
            #pragma unroll
            for (int mi = 0; mi < 2; mi++) {
                uint32_t ad = (sb + AQ_OFF + q * 16384 + tile_off(R + mi * 16 + laneA, cA)) ^ ko;
                asm volatile(
                    "ldmatrix.sync.aligned.m8n8.x4.shared.b16 {%0,%1,%2,%3}, [%4];"
                    : "=r"(a[mi][0]), "=r"(a[mi][1]), "=r"(a[mi][2]), "=r"(a[mi][3])
                    : "r"(ad));
            }
            #pragma unroll
            for (int p = 0; p < 4; p++) {
                uint32_t ad = (sb + AK_OFF + q * 16384 + tile_off(blk * 64 + p * 16 + laneB, cBi)) ^ ko;
                asm volatile(
                    "ldmatrix.sync.aligned.m8n8.x4.shared.b16 {%0,%1,%2,%3}, [%4];"
                    : "=r"(bk[2*p][0]), "=r"(bk[2*p][1]), "=r"(bk[2*p+1][0]), "=r"(bk[2*p+1][1])
                    : "r"(ad));
            }
            #pragma unroll
            for (int mi = 0; mi < 2; mi++)
                #pragma unroll
                for (int ni = 0; ni < 8; ni++) {
                    asm volatile(
                        "mma.sync.aligned.m16n8k16.row.col.f32.bf16.bf16.f32 "
                        "{%0,%1,%2,%3}, {%4,%5,%6,%7}, {%8,%9}, {%0,%1,%2,%3};"
                        : "+f"(s[mi][ni][0]), "+f"(s[mi][ni][1]),
                          "+f"(s[mi][ni][2]), "+f"(s[mi][ni][3])
                        : "r"(a[mi][0]), "r"(a[mi][1]), "r"(a[mi][2]), "r"(a[mi][3]),
                          "r"(bk[ni][0]), "r"(bk[ni][1]));
                }
        }

        #pragma unroll
        for (int mi = 0; mi < 2; mi++)
            #pragma unroll
            for (int ni = 0; ni < 8; ni++)
                #pragma unroll
                for (int r = 0; r < 4; r++) s[mi][ni][r] *= 0.125f;

        #pragma unroll
        for (int mi = 0; mi < 2; mi++) {
            #pragma unroll
            for (int hf = 0; hf < 2; hf++) {
                float bm = -1e30f;
                #pragma unroll
                for (int ni = 0; ni < 8; ni++) {
                    bm = fmaxf(bm, s[mi][ni][hf*2]);
                    bm = fmaxf(bm, s[mi][ni][hf*2+1]);
                }
                bm = fmaxf(bm, __shfl_xor_sync(0xffffffffu, bm, 1));
                bm = fmaxf(bm, __shfl_xor_sync(0xffffffffu, bm, 2));
                float mnew = fmaxf(mrow[mi][hf], bm);
                float corr = __expf(mrow[mi][hf] - mnew);
                mrow[mi][hf] = mnew;
                float rs = 0.f;
                #pragma unroll
                for (int ni = 0; ni < 8; ni++) {
                    float e0 = __expf(s[mi][ni][hf*2]   - mnew);
                    float e1 = __expf(s[mi][ni][hf*2+1] - mnew);
                    s[mi][ni][hf*2]   = e0;
                    s[mi][ni][hf*2+1] = e1;
                    rs += e0 + e1;
                }
                rs += __shfl_xor_sync(0xffffffffu, rs, 1);
                rs += __shfl_xor_sync(0xffffffffu, rs, 2);
                lrow[mi][hf] = lrow[mi][hf] * corr + rs;
                #pragma unroll
                for (int ni = 0; ni < 8; ni++) {
                    o[mi][ni][hf*2]   *= corr;
                    o[mi][ni][hf*2+1] *= corr;
                }
            }
        }

        uint32_t pa[2][4][4];
        #pragma unroll
        for (int mi = 0; mi < 2; mi++)
            #pragma unroll
            for (int st = 0; st < 4; st++) {
                pa[mi][st][0] = packbf(s[mi][2*st][0],   s[mi][2*st][1]);
                pa[mi][st][1] = packbf(s[mi][2*st][2],   s[mi][2*st][3]);
                pa[mi][st][2] = packbf(s[mi][2*st+1][0], s[mi][2*st+1][1]);
                pa[mi][st][3] = packbf(s[mi][2*st+1][2], s[mi][2*st+1][3]);
            }

        #pragma unroll
        for (int st = 0; st < 4; st++) {
            const int vc = blk * 2 + (st >> 1);
            const uint32_t ko = (uint32_t)((st & 1) * 32);
            uint32_t vb[8][2];
            #pragma unroll
            for (int pd = 0; pd < 4; pd++) {
                uint32_t ad = (sb + AV_OFF + vc * 4096 + tile_off(pd * 16 + laneB, cBi)) ^ ko;
                asm volatile(
                    "ldmatrix.sync.aligned.m8n8.x4.shared.b16 {%0,%1,%2,%3}, [%4];"
                    : "=r"(vb[2*pd][0]), "=r"(vb[2*pd][1]), "=r"(vb[2*pd+1][0]), "=r"(vb[2*pd+1][1])
                    : "r"(ad));
            }
            #pragma unroll
            for (int mi = 0; mi < 2; mi++)
                #pragma unroll
                for (int di = 0; di < 8; di++) {
                    asm volatile(
                        "mma.sync.aligned.m16n8k16.row.col.f32.bf16.bf16.f32 "
                        "{%0,%1,%2,%3}, {%4,%5,%6,%7}, {%8,%9}, {%0,%1,%2,%3};"
                        : "+f"(o[mi][di][0]), "+f"(o[mi][di][1]),
                          "+f"(o[mi][di][2]), "+f"(o[mi][di][3])
                        : "r"(pa[mi][st][0]), "r"(pa[mi][st][1]),
                          "r"(pa[mi][st][2]), "r"(pa[mi][st][3]),
                          "r"(vb[di][0]), "r"(vb[di][1]));
                }
        }
    }

    #pragma unroll
    for (int mi = 0; mi < 2; mi++) {
        #pragma unroll
        for (int hf = 0; hf < 2; hf++) {
            int row = tbase + R + mi * 16 + g + hf * 8;
            float inv = 1.0f / lrow[mi][hf];
            #pragma unroll
            for (int ni = 0; ni < 8; ni++) {
                __nv_bfloat162 h2 = __floats2bfloat162_rn(o[mi][ni][hf*2] * inv,
                                                          o[mi][ni][hf*2+1] * inv);
                *(__nv_bfloat162*)(out + (size_t)row * DIM + hoff + ni * 8 + t4 * 2) = h2;
            }
        }
    }
}

// ---------------- biattn pieces ----------------
__global__ void mean_k(const __nv_bfloat16* __restrict__ bx, __nv_bfloat16* __restrict__ xg)
{
    int idx = blockIdx.x * blockDim.x + threadIdx.x;
    if (idx >= BB * NN * DIM) return;
    int d = idx % DIM;
    int n = (idx / DIM) % NN;
    int b = idx / (DIM * NN);
    size_t base = ((size_t)(b * PP) * NN + n) * DIM + d;
    const size_t st = (size_t)NN * DIM;
    float s = __bfloat162float(bx[base]) + __bfloat162float(bx[base + st])
            + __bfloat162float(bx[base + 2*st]) + __bfloat162float(bx[base + 3*st]);
    xg[idx] = __float2bfloat16(0.25f * s);
}

__global__ __launch_bounds__(256)
void sattn_k(const __nv_bfloat16* __restrict__ xl, const __nv_bfloat16* __restrict__ xga,
             const float* __restrict__ ws, const float* __restrict__ bsc,
             float* __restrict__ sa)
{
    int gtid = blockIdx.x * 256 + threadIdx.x;
    int t = gtid >> 5;
    int lane = threadIdx.x & 31;
    if (t >= TT) return;
    int b = t / (PP * NN);
    int n = t % NN;
    const __nv_bfloat16* xlp = xl  + (size_t)t * RED;
    const __nv_bfloat16* xgp = xga + ((size_t)b * NN + n) * RED;
    float s = 0.f;
    for (int i = lane; i < RED; i += 32)
        s += __bfloat162float(xlp[i]) * ws[i] + __bfloat162float(xgp[i]) * ws[RED + i];
    #pragma unroll
    for (int o = 16; o; o >>= 1) s += __shfl_xor_sync(0xffffffffu, s, o);
    if (lane == 0) sa[t] = 1.0f / (1.0f + __expf(-(s + bsc[0])));
}

__global__ void fuse_k(const float* __restrict__ h, const float* __restrict__ ca,
                       const float* __restrict__ sa, const float* __restrict__ x,
                       float* __restrict__ out)
{
    int idx = blockIdx.x * blockDim.x + threadIdx.x;
    if (idx >= TT * DIM) return;
    int t = idx / DIM;
    int d = idx % DIM;
    int b = t / (PP * NN);
    int n = t % NN;
    out[idx] = x[idx] + h[idx] * ca[((size_t)b * NN + n) * DIM + d] * sa[t];
}

// ---------------- host driver ----------------
extern "C" void kernel_launch(void* const* d_in, const int* in_sizes, int n_in,
                              void* d_out, int out_size)
{
    const float* x_in  = (const float*)d_in[0];
    const float* ln1_g = (const float*)d_in[1];
    const float* ln1_b = (const float*)d_in[2];
    const float* w_qkv = (const float*)d_in[3];
    const float* w_o   = (const float*)d_in[4];
    const float* b_o   = (const float*)d_in[5];
    const float* ln2_g = (const float*)d_in[6];
    const float* ln2_b = (const float*)d_in[7];
    const float* w1    = (const float*)d_in[8];
    const float* b1    = (const float*)d_in[9];
    const float* w2    = (const float*)d_in[10];
    const float* b2    = (const float*)d_in[11];
    const float* bn_g  = (const float*)d_in[12];
    const float* bn_b  = (const float*)d_in[13];
    const float* wg    = (const float*)d_in[14];
    const float* bg    = (const float*)d_in[15];
    const float* wl    = (const float*)d_in[16];
    const float* bl    = (const float*)d_in[17];
    const float* wc    = (const float*)d_in[18];
    const float* bc    = (const float*)d_in[19];
    const float* ws    = (const float*)d_in[20];
    const float* bs    = (const float*)d_in[21];

    float* base = nullptr;
    cudaGetSymbolAddress((void**)&base, g_scratch);
    float*          X   = base + OFF_X;
    __nv_bfloat16*  Y   = (__nv_bfloat16*)(base + OFF_Y);
    __nv_bfloat16*  QKV = (__nv_bfloat16*)(base + OFF_QKV);
    __nv_bfloat16*  ATT = (__nv_bfloat16*)(base + OFF_ATT);
    __nv_bfloat16*  H1  = (__nv_bfloat16*)(base + OFF_H1);
    float*          H   = base + OFF_H;
    __nv_bfloat16*  BX  = (__nv_bfloat16*)(base + OFF_BX);
    __nv_bfloat16*  XG  = (__nv_bfloat16*)(base + OFF_XG);
    __nv_bfloat16*  XGA = (__nv_bfloat16*)(base + OFF_XGA);
    __nv_bfloat16*  XL  = (__nv_bfloat16*)(base + OFF_XL);
    float*          CA  = base + OFF_CA;
    float*          SA  = base + OFF_SA;
    __nv_bfloat16*  WT  = (__nv_bfloat16*)(base + OFF_WT);

    cudaFuncSetAttribute((const void*)attn2_k,
                         cudaFuncAttributeMaxDynamicSharedMemorySize, ATT2_SMEM);
    cudaFuncSetAttribute((const void*)bgemm_k<EPI_NONE,1>,
                         cudaFuncAttributeMaxDynamicSharedMemorySize, GSMEM);
    cudaFuncSetAttribute((const void*)bgemm_k<EPI_RES,0>,
                         cudaFuncAttributeMaxDynamicSharedMemorySize, GSMEM);
    cudaFuncSetAttribute((const void*)bgemm_k<EPI_GELU,1>,
                         cudaFuncAttributeMaxDynamicSharedMemorySize, GSMEM);
    cudaFuncSetAttribute((const void*)bgemm_k<EPI_BIAS,0>,
                         cudaFuncAttributeMaxDynamicSharedMemorySize, GSMEM);
    cudaFuncSetAttribute((const void*)bgemm_k<EPI_SIG,0>,
                         cudaFuncAttributeMaxDynamicSharedMemorySize, GSMEM);

    const int EW = 256;
    dim3 tp(32, 8);

    // transpose-pack all weights to [d][n][k] bf16 (once per launch)
    packwt_k<<<dim3(512/32, 1536/32, 4), tp>>>(w_qkv, WT + WT_QKV, 512, 1536);
    packwt_k<<<dim3(512/32,  512/32, 4), tp>>>(w_o,   WT + WT_O,   512,  512);
    packwt_k<<<dim3(512/32, 2048/32, 4), tp>>>(w1,    WT + WT_W1,  512, 2048);
    packwt_k<<<dim3(2048/32, 512/32, 4), tp>>>(w2,    WT + WT_W2, 2048,  512);
    packwt_k<<<dim3(512/32,  128/32, 4), tp>>>(wg,    WT + WT_WG,  512,  128);
    packwt_k<<<dim3(512/32,  128/32, 4), tp>>>(wl,    WT + WT_WL,  512,  128);
    packwt_k<<<dim3(128/32,  512/32, 4), tp>>>(wc,    WT + WT_WC,  128,  512);

    for (int l = 0; l < DEPTH; l++) {
        const float* Xin = (l == 0) ? x_in : X;

        // ---- attention half ----
        ln_k<<<TT, 128>>>(Xin, Y, ln1_g + l*DIM, ln1_b + l*DIM);
        bgemm_k<EPI_NONE,1><<<dim3(3*DIM/128, TT/128), 256, GSMEM>>>(
            Y, WT + WT_QKV + (size_t)l*1536*512, QKV, TT, 3*DIM, DIM, nullptr, nullptr);
        attn2_k<<<BB*PP*HEADS, 256, ATT2_SMEM>>>(QKV, ATT);
        bgemm_k<EPI_RES,0><<<dim3(DIM/128, TT/128), 256, GSMEM>>>(
            ATT, WT + WT_O + (size_t)l*512*512, X, TT, DIM, DIM, b_o + l*DIM, Xin);

        // ---- mlp half ----
        ln_k<<<TT, 128>>>(X, Y, ln2_g + l*DIM, ln2_b + l*DIM);
        bgemm_k<EPI_GELU,1><<<dim3(MLPD/128, TT/128), 256, GSMEM>>>(
            Y, WT + WT_W1 + (size_t)l*2048*512, H1, TT, MLPD, DIM, b1 + l*MLPD, nullptr);
        bgemm_k<EPI_BIAS,0><<<dim3(DIM/128, TT/128), 256, GSMEM>>>(
            H1, WT + WT_W2 + (size_t)l*512*2048, H, TT, DIM, MLPD, b2 + l*DIM, nullptr);

        // ---- biattn ----
        ln_k<<<TT, 128>>>(H, BX, bn_g + l*DIM, bn_b + l*DIM);
        mean_k<<<(BB*NN*DIM + EW - 1) / EW, EW>>>(BX, XG);
        bgemm_k<EPI_GELU,1><<<dim3(RED/128, BB*NN/128), 256, GSMEM>>>(
            XG, WT + WT_WG + (size_t)l*128*512, XGA, BB*NN, RED, DIM, bg + l*RED, nullptr);
        bgemm_k<EPI_GELU,1><<<dim3(RED/128, TT/128), 256, GSMEM>>>(
            BX, WT + WT_WL + (size_t)l*128*512, XL, TT, RED, DIM, bl + l*RED, nullptr);
        bgemm_k<EPI_SIG,0><<<dim3(DIM/128, BB*NN/128), 256, GSMEM>>>(
            XGA, WT + WT_WC + (size_t)l*512*128, CA, BB*NN, DIM, RED, bc + l*DIM, nullptr);
        sattn_k<<<(TT*32 + 255) / 256, 256>>>(XL, XGA, ws + l*2*RED, bs + l, SA);

        float* fuse_out = (l == DEPTH - 1) ? (float*)d_out : X;
        fuse_k<<<(TT*DIM + EW - 1) / EW, EW>>>(H, CA, SA, X, fuse_out);
    }
}

// round 17
// speedup vs baseline: 2.9879x; 1.0826x over previous
#include <cuda_runtime.h>
#include <cuda_bf16.h>
#include <cstdint>

// ---------------- problem constants ----------------
#define DEPTH  4
#define HEADS  8
#define DHEAD  64
#define DIM    512
#define MLPD   2048
#define RED    128
#define BB     8
#define PP     4
#define NN     256
#define TT     (BB*PP*NN)     // 8192 tokens

// ---------------- scratch ----------------
static const size_t OFF_X   = 0;                               // f32 residual
static const size_t OFF_Y   = OFF_X   + (size_t)TT*DIM;        // bf16 LN out
static const size_t OFF_QKV = OFF_Y   + (size_t)TT*DIM;        // bf16
static const size_t OFF_ATT = OFF_QKV + (size_t)TT*3*DIM;      // bf16
static const size_t OFF_H1  = OFF_ATT + (size_t)TT*DIM;        // bf16
static const size_t OFF_H   = OFF_H1  + (size_t)TT*MLPD;       // f32
static const size_t OFF_BX  = OFF_H   + (size_t)TT*DIM;        // bf16
static const size_t OFF_XG  = OFF_BX  + (size_t)TT*DIM;        // bf16
static const size_t OFF_XGA = OFF_XG  + (size_t)BB*NN*DIM;     // bf16
static const size_t OFF_XL  = OFF_XGA + (size_t)BB*NN*RED;     // bf16
static const size_t OFF_CA  = OFF_XL  + (size_t)TT*RED;        // f32
static const size_t OFF_SA  = OFF_CA  + (size_t)BB*NN*DIM;     // f32
static const size_t OFF_WT  = OFF_SA  + TT;                    // transposed bf16 weights

// transposed-weight sub-offsets (bf16 element units): layout [d][n][k]
static const size_t WT_QKV = 0;
static const size_t WT_O   = WT_QKV + (size_t)4*1536*512;
static const size_t WT_W1  = WT_O   + (size_t)4*512*512;
static const size_t WT_W2  = WT_W1  + (size_t)4*2048*512;
static const size_t WT_WG  = WT_W2  + (size_t)4*512*2048;
static const size_t WT_WL  = WT_WG  + (size_t)4*128*512;
static const size_t WT_WC  = WT_WL  + (size_t)4*128*512;
static const size_t WT_TOT = WT_WC  + (size_t)4*512*128;

static const size_t SCRATCH_FLOATS = OFF_WT + (WT_TOT + 1) / 2;

__device__ float g_scratch[SCRATCH_FLOATS];

// ---------------- helpers ----------------
__device__ __forceinline__ uint32_t smem_u32(const void* p) {
    uint32_t a;
    asm("{ .reg .u64 t; cvta.to.shared.u64 t, %1; cvt.u32.u64 %0, t; }" : "=r"(a) : "l"(p));
    return a;
}
__device__ __forceinline__ void cp16(uint32_t dst, const void* src) {
    asm volatile("cp.async.cg.shared.global [%0], [%1], 16;\n" :: "r"(dst), "l"(src));
}
__device__ __forceinline__ void cp_commit() {
    asm volatile("cp.async.commit_group;\n");
}
template<int N>
__device__ __forceinline__ void cp_wait() {
    asm volatile("cp.async.wait_group %0;\n" :: "n"(N));
}
__device__ __forceinline__ uint32_t packbf(float x, float y) {
    __nv_bfloat162 h = __floats2bfloat162_rn(x, y);
    return *reinterpret_cast<uint32_t*>(&h);
}
// verified swizzled tile layout: row r, 16B chunk c (0..3), 64B per row
// k16 sub-step (c -> c+2) on the swizzled address is addr ^ 32 (NOT +32).
__device__ __forceinline__ uint32_t tile_off(int r, int c) {
    return (uint32_t)((r >> 1) * 128 + (((4 * (r & 1) + c) ^ ((r >> 1) & 7)) * 16));
}

// ---------------- merged transpose-pack: all 7 weights in one launch ------
// W[d][K][N] f32 -> Wt[d][N][K] bf16, 32x32 tiles (body proven round 10).
// grid.x = 13056 flattened tiles; if-chain segment table.
__global__ void packall_k(const float* __restrict__ w_qkv, const float* __restrict__ w_o,
                          const float* __restrict__ w1,    const float* __restrict__ w2,
                          const float* __restrict__ wg,    const float* __restrict__ wl,
                          const float* __restrict__ wc,    __nv_bfloat16* __restrict__ WT)
{
    int bid = blockIdx.x;
    const float* W; __nv_bfloat16* Out; int K, N, local;
    if      (bid <  3072) { W = w_qkv; Out = WT + WT_QKV; K = 512;  N = 1536; local = bid;         }
    else if (bid <  4096) { W = w_o;   Out = WT + WT_O;   K = 512;  N = 512;  local = bid - 3072;  }
    else if (bid <  8192) { W = w1;    Out = WT + WT_W1;  K = 512;  N = 2048; local = bid - 4096;  }
    else if (bid < 12288) { W = w2;    Out = WT + WT_W2;  K = 2048; N = 512;  local = bid - 8192;  }
    else if (bid < 12544) { W = wg;    Out = WT + WT_WG;  K = 512;  N = 128;  local = bid - 12288; }
    else if (bid < 12800) { W = wl;    Out = WT + WT_WL;  K = 512;  N = 128;  local = bid - 12544; }
    else                  { W = wc;    Out = WT + WT_WC;  K = 128;  N = 512;  local = bid - 12800; }
    const int kt = K >> 5, nt = N >> 5;
    const int d   = local / (kt * nt);
    const int rem = local % (kt * nt);
    const int k0 = (rem % kt) * 32, n0 = (rem / kt) * 32;

    __shared__ float t[32][33];
    const float* Wd = W + (size_t)d * K * N;
    #pragma unroll
    for (int i = 0; i < 32; i += 8)
        t[threadIdx.y + i][threadIdx.x] =
            Wd[(size_t)(k0 + threadIdx.y + i) * N + n0 + threadIdx.x];
    __syncthreads();
    __nv_bfloat16* out = Out + (size_t)d * N * K;
    #pragma unroll
    for (int i = 0; i < 32; i += 8)
        out[(size_t)(n0 + threadIdx.y + i) * K + k0 + threadIdx.x] =
            __float2bfloat16(t[threadIdx.x][threadIdx.y + i]);
}

// ---------------- layernorm: fp32 in, bf16 out ----------------
__global__ __launch_bounds__(128)
void ln_k(const float* __restrict__ in, __nv_bfloat16* __restrict__ out,
          const float* __restrict__ g, const float* __restrict__ b)
{
    int t = blockIdx.x;
    int lane = threadIdx.x & 31, w = threadIdx.x >> 5;
    float4 v = ((const float4*)(in + (size_t)t*DIM))[threadIdx.x];
    float s = v.x + v.y + v.z + v.w;
    float q = v.x*v.x + v.y*v.y + v.z*v.z + v.w*v.w;
    #pragma unroll
    for (int o = 16; o; o >>= 1) {
        s += __shfl_xor_sync(0xffffffffu, s, o);
        q += __shfl_xor_sync(0xffffffffu, q, o);
    }
    __shared__ float ss[4], qq[4];
    if (lane == 0) { ss[w] = s; qq[w] = q; }
    __syncthreads();
    s = ss[0] + ss[1] + ss[2] + ss[3];
    q = qq[0] + qq[1] + qq[2] + qq[3];
    float mean = s * (1.0f / DIM);
    float var  = q * (1.0f / DIM) - mean * mean;
    float inv  = rsqrtf(var + 1e-5f);
    float4 gg = ((const float4*)g)[threadIdx.x];
    float4 bb = ((const float4*)b)[threadIdx.x];
    float o0 = (v.x - mean) * inv * gg.x + bb.x;
    float o1 = (v.y - mean) * inv * gg.y + bb.y;
    float o2 = (v.z - mean) * inv * gg.z + bb.z;
    float o3 = (v.w - mean) * inv * gg.w + bb.w;
    __nv_bfloat162* op = (__nv_bfloat162*)(out + (size_t)t*DIM) + 2*threadIdx.x;
    op[0] = __floats2bfloat162_rn(o0, o1);
    op[1] = __floats2bfloat162_rn(o2, o3);
}

// ---------------- fused biattn-residual + next-layer LN -------------------
// f = x + h*ca*sa ; write f to xout; if !LAST also write LN(f) bf16 to yout.
template<int LAST>
__global__ __launch_bounds__(128)
void fuseln_k(const float* __restrict__ h, const float* __restrict__ ca,
              const float* __restrict__ sa, const float* __restrict__ x,
              float* __restrict__ xout, __nv_bfloat16* __restrict__ yout,
              const float* __restrict__ g, const float* __restrict__ b)
{
    int t = blockIdx.x;
    int bi = t / (PP * NN), n = t % NN;
    float4 xv = ((const float4*)(x + (size_t)t*DIM))[threadIdx.x];
    float4 hv = ((const float4*)(h + (size_t)t*DIM))[threadIdx.x];
    float4 cv = ((const float4*)(ca + ((size_t)bi*NN + n)*DIM))[threadIdx.x];
    float sv = sa[t];
    float4 f;
    f.x = xv.x + hv.x * cv.x * sv;
    f.y = xv.y + hv.y * cv.y * sv;
    f.z = xv.z + hv.z * cv.z * sv;
    f.w = xv.w + hv.w * cv.w * sv;
    ((float4*)(xout + (size_t)t*DIM))[threadIdx.x] = f;
    if (LAST) return;

    int lane = threadIdx.x & 31, w = threadIdx.x >> 5;
    float s = f.x + f.y + f.z + f.w;
    float q = f.x*f.x + f.y*f.y + f.z*f.z + f.w*f.w;
    #pragma unroll
    for (int o = 16; o; o >>= 1) {
        s += __shfl_xor_sync(0xffffffffu, s, o);
        q += __shfl_xor_sync(0xffffffffu, q, o);
    }
    __shared__ float ss[4], qq[4];
    if (lane == 0) { ss[w] = s; qq[w] = q; }
    __syncthreads();
    s = ss[0] + ss[1] + ss[2] + ss[3];
    q = qq[0] + qq[1] + qq[2] + qq[3];
    float mean = s * (1.0f / DIM);
    float var  = q * (1.0f / DIM) - mean * mean;
    float inv  = rsqrtf(var + 1e-5f);
    float4 gg = ((const float4*)g)[threadIdx.x];
    float4 bb = ((const float4*)b)[threadIdx.x];
    float o0 = (f.x - mean) * inv * gg.x + bb.x;
    float o1 = (f.y - mean) * inv * gg.y + bb.y;
    float o2 = (f.z - mean) * inv * gg.z + bb.z;
    float o3 = (f.w - mean) * inv * gg.w + bb.w;
    __nv_bfloat162* op = (__nv_bfloat162*)(yout + (size_t)t*DIM) + 2*threadIdx.x;
    op[0] = __floats2bfloat162_rn(o0, o1);
    op[1] = __floats2bfloat162_rn(o2, o3);
}

// ---------------- bf16 GEMM: ldmatrix + 4-stage cp.async (proven r16) -----
// C[M,N] = A[M,K] @ Bt[N,K]^T (+ epilogue). Template BM in {128, 64}.
// BN=128 fixed; 8 warps 2x4; warp tile (BM/2)x32.
#define EPI_NONE 0
#define EPI_BIAS 1
#define EPI_GELU 2
#define EPI_SIG  3
#define EPI_RES  4

#define GST 4

template<int EPI, int OBF, int BM>
__global__ __launch_bounds__(256, 2)
void bgemm_k(const __nv_bfloat16* __restrict__ Abf, const __nv_bfloat16* __restrict__ Bt,
             void* __restrict__ Cout, int M, int N, int K,
             const float* __restrict__ bias, const float* __restrict__ res)
{
    constexpr int MI    = BM / 32;        // mi steps per warp (4 or 2)
    constexpr int TILEA = BM * 64;        // bytes per A stage tile
    constexpr int STAGE = TILEA + 8192;   // + B tile (128 rows x 64B)

    extern __shared__ __align__(1024) uint8_t dsm[];
    const uint32_t sbase = smem_u32(dsm);

    const int tid   = threadIdx.x;
    const int warp  = tid >> 5, lane = tid & 31;
    const int group = lane >> 2, tig = lane & 3;
    const int wm = (warp >> 2) * (BM / 2);
    const int wn = (warp & 3) * 32;
    const int m0 = blockIdx.y * BM, n0 = blockIdx.x * 128;

    auto stage_cp = [&](int kt, int s) {
        #pragma unroll
        for (int i = 0; i < BM / 64; i++) {
            int idx = i * 256 + tid;
            int r = idx >> 2, c = idx & 3;
            cp16(sbase + s * STAGE + tile_off(r, c),
                 Abf + (size_t)(m0 + r) * K + kt * 32 + c * 8);
        }
        #pragma unroll
        for (int i = 0; i < 2; i++) {
            int idx = i * 256 + tid;
            int r = idx >> 2, c = idx & 3;
            cp16(sbase + s * STAGE + TILEA + tile_off(r, c),
                 Bt + (size_t)(n0 + r) * K + kt * 32 + c * 8);
        }
        cp_commit();
    };

    const int rA = wm + (lane & 7) + ((lane >> 3) & 1) * 8;
    const int cA = (lane >> 4) & 1;
    const uint32_t aBase = sbase + tile_off(rA, cA);
    const int rB = wn + (lane & 7) + ((lane >> 4) & 1) * 8;
    const int cB = (lane >> 3) & 1;
    const uint32_t bBase = sbase + TILEA + tile_off(rB, cB);

    const int nk = K / 32;

    stage_cp(0, 0);
    stage_cp(1, 1);
    stage_cp(2, 2);
    cp_wait<2>();
    __syncthreads();

    float acc[MI][4][4];
    #pragma unroll
    for (int mi = 0; mi < MI; mi++)
        #pragma unroll
        for (int ni = 0; ni < 4; ni++)
            #pragma unroll
            for (int r = 0; r < 4; r++) acc[mi][ni][r] = 0.f;

    for (int kt = 0; kt < nk; kt++) {
        const int buf = kt & 3;
        const uint32_t abuf = aBase + buf * STAGE;
        const uint32_t bbuf = bBase + buf * STAGE;

        if (kt + 3 < nk) stage_cp(kt + 3, (kt + 3) & 3);
        else             cp_commit();

        #pragma unroll
        for (int k16 = 0; k16 < 2; k16++) {
            const uint32_t koff = k16 ? 32u : 0u;
            uint32_t a[MI][4], b[4][2];
            #pragma unroll
            for (int mi = 0; mi < MI; mi++) {
                asm volatile(
                    "ldmatrix.sync.aligned.m8n8.x4.shared.b16 {%0,%1,%2,%3}, [%4];"
                    : "=r"(a[mi][0]), "=r"(a[mi][1]), "=r"(a[mi][2]), "=r"(a[mi][3])
                    : "r"((abuf + mi * 1024u) ^ koff));
            }
            #pragma unroll
            for (int p = 0; p < 2; p++) {
                asm volatile(
                    "ldmatrix.sync.aligned.m8n8.x4.shared.b16 {%0,%1,%2,%3}, [%4];"
                    : "=r"(b[2*p][0]), "=r"(b[2*p][1]), "=r"(b[2*p+1][0]), "=r"(b[2*p+1][1])
                    : "r"((bbuf + p * 1024u) ^ koff));
            }
            #pragma unroll
            for (int mi = 0; mi < MI; mi++)
                #pragma unroll
                for (int ni = 0; ni < 4; ni++) {
                    asm volatile(
                        "mma.sync.aligned.m16n8k16.row.col.f32.bf16.bf16.f32 "
                        "{%0,%1,%2,%3}, {%4,%5,%6,%7}, {%8,%9}, {%0,%1,%2,%3};"
                        : "+f"(acc[mi][ni][0]), "+f"(acc[mi][ni][1]),
                          "+f"(acc[mi][ni][2]), "+f"(acc[mi][ni][3])
                        : "r"(a[mi][0]), "r"(a[mi][1]), "r"(a[mi][2]), "r"(a[mi][3]),
                          "r"(b[ni][0]), "r"(b[ni][1]));
                }
        }

        cp_wait<2>();
        __syncthreads();
    }

    #pragma unroll
    for (int mi = 0; mi < MI; mi++) {
        #pragma unroll
        for (int half = 0; half < 2; half++) {
            int m = m0 + wm + mi * 16 + group + half * 8;
            #pragma unroll
            for (int ni = 0; ni < 4; ni++) {
                int n = n0 + wn + ni * 8 + tig * 2;
                float v0 = acc[mi][ni][half * 2 + 0];
                float v1 = acc[mi][ni][half * 2 + 1];
                if (EPI != EPI_NONE) { v0 += bias[n]; v1 += bias[n + 1]; }
                if (EPI == EPI_GELU) {
                    v0 = 0.5f * v0 * (1.0f + erff(v0 * 0.70710678118654752f));
                    v1 = 0.5f * v1 * (1.0f + erff(v1 * 0.70710678118654752f));
                } else if (EPI == EPI_SIG) {
                    v0 = 1.0f / (1.0f + __expf(-v0));
                    v1 = 1.0f / (1.0f + __expf(-v1));
                } else if (EPI == EPI_RES) {
                    v0 += res[(size_t)m * N + n];
                    v1 += res[(size_t)m * N + n + 1];
                }
                if (OBF) {
                    __nv_bfloat162 h2 = __floats2bfloat162_rn(v0, v1);
                    *(__nv_bfloat162*)((__nv_bfloat16*)Cout + (size_t)m * N + n) = h2;
                } else {
                    *(float2*)((float*)Cout + (size_t)m * N + n) = make_float2(v0, v1);
                }
            }
        }
    }
}

#define GSMEM128 (GST*(128*64+8192))
#define GSMEM64  (GST*(64*64+8192))

// ---------------- flash attention (tensor cores, proven round-14) ---------
#define AQ_OFF 0
#define AK_OFF 32768
#define AV_OFF 65536
#define ATT2_SMEM (96*1024)

__global__ __launch_bounds__(256)
void attn2_k(const __nv_bfloat16* __restrict__ qkv, __nv_bfloat16* __restrict__ out)
{
    extern __shared__ __align__(1024) uint8_t sm8[];
    const uint32_t sb = smem_u32(sm8);
    const int tid = threadIdx.x;
    const int h = blockIdx.x & 7, bp = blockIdx.x >> 3;
    const int tbase = bp * NN, hoff = h * DHEAD;

    for (int idx = tid; idx < 2048; idx += 256) {
        int r = idx >> 3, u = idx & 7;
        int q = u >> 2, c = u & 3;
        const __nv_bfloat16* rowp = qkv + (size_t)(tbase + r) * 1536;
        *(uint4*)(sm8 + AQ_OFF + q * 16384 + tile_off(r, c)) =
            *(const uint4*)(rowp + hoff + q * 32 + c * 8);
        *(uint4*)(sm8 + AK_OFF + q * 16384 + tile_off(r, c)) =
            *(const uint4*)(rowp + 512 + hoff + q * 32 + c * 8);
    }
    for (int idx = tid; idx < 2048; idx += 256) {
        int r = idx >> 3, u = idx & 7;
        uint4 v = *(const uint4*)(qkv + (size_t)(tbase + r) * 1536 + 1024 + hoff + u * 8);
        const __nv_bfloat16* pv = (const __nv_bfloat16*)&v;
        int chunk = r >> 5, col = r & 31, cc = col >> 3, wi = col & 7;
        #pragma unroll
        for (int j = 0; j < 8; j++) {
            int d = u * 8 + j;
            uint32_t a = AV_OFF + chunk * 4096 + (d >> 1) * 128
                       + (((4 * (d & 1) + cc) ^ ((d >> 1) & 7)) * 16) + wi * 2;
            *(__nv_bfloat16*)(sm8 + a) = pv[j];
        }
    }
    __syncthreads();

    const int warp = tid >> 5, lane = tid & 31;
    const int g = lane >> 2, t4 = lane & 3;
    const int R = warp * 32;
    const int laneA = (lane & 7) + ((lane >> 3) & 1) * 8;
    const int cA    = (lane >> 4) & 1;
    const int laneB = (lane & 7) + ((lane >> 4) & 1) * 8;
    const int cBi   = (lane >> 3) & 1;

    float mrow[2][2], lrow[2][2];
    float o[2][8][4];
    #pragma unroll
    for (int mi = 0; mi < 2; mi++)
        #pragma unroll
        for (int hf = 0; hf < 2; hf++) { mrow[mi][hf] = -1e30f; lrow[mi][hf] = 0.f; }
    #pragma unroll
    for (int mi = 0; mi < 2; mi++)
        #pragma unroll
        for (int ni = 0; ni < 8; ni++)
            #pragma unroll
            for (int r = 0; r < 4; r++) o[mi][ni][r] = 0.f;

    for (int blk = 0; blk < 4; blk++) {
        float s[2][8][4];
        #pragma unroll
        for (int mi = 0; mi < 2; mi++)
            #pragma unroll
            for (int ni = 0; ni < 8; ni++)
                #pragma unroll
                for (int r = 0; r < 4; r++) s[mi][ni][r] = 0.f;

        #pragma unroll
        for (int st = 0; st < 4; st++) {
            const int q = st >> 1;
            const uint32_t ko = (uint32_t)((st & 1) * 32);
            uint32_t a[2][4], bk[8][2];
            #pragma unroll
            for (int mi = 0; mi < 2; mi++) {
                uint32_t ad = (sb + AQ_OFF + q * 16384 + tile_off(R + mi * 16 + laneA, cA)) ^ ko;
                asm volatile(
                    "ldmatrix.sync.aligned.m8n8.x4.shared.b16 {%0,%1,%2,%3}, [%4];"
                    : "=r"(a[mi][0]), "=r"(a[mi][1]), "=r"(a[mi][2]), "=r"(a[mi][3])
                    : "r"(ad));
            }
            #pragma unroll
            for (int p = 0; p < 4; p++) {
                uint32_t ad = (sb + AK_OFF + q * 16384 + tile_off(blk * 64 + p * 16 + laneB, cBi)) ^ ko;
                asm volatile(
                    "ldmatrix.sync.aligned.m8n8.x4.shared.b16 {%0,%1,%2,%3}, [%4];"
                    : "=r"(bk[2*p][0]), "=r"(bk[2*p][1]), "=r"(bk[2*p+1][0]), "=r"(bk[2*p+1][1])
                    : "r"(ad));
            }
            #pragma unroll
            for (int mi = 0; mi < 2; mi++)
                #pragma unroll
                for (int ni = 0; ni < 8; ni++) {
                    asm volatile(
                        "mma.sync.aligned.m16n8k16.row.col.f32.bf16.bf16.f32 "
                        "{%0,%1,%2,%3}, {%4,%5,%6,%7}, {%8,%9}, {%0,%1,%2,%3};"
                        : "+f"(s[mi][ni][0]), "+f"(s[mi][ni][1]),
                          "+f"(s[mi][ni][2]), "+f"(s[mi][ni][3])
                        : "r"(a[mi][0]), "r"(a[mi][1]), "r"(a[mi][2]), "r"(a[mi][3]),
                          "r"(bk[ni][0]), "r"(bk[ni][1]));
                }
        }

        #pragma unroll
        for (int mi = 0; mi < 2; mi++)
            #pragma unroll
            for (int ni = 0; ni < 8; ni++)
                #pragma unroll
                for (int r = 0; r < 4; r++) s[mi][ni][r] *= 0.125f;

        #pragma unroll
        for (int mi = 0; mi < 2; mi++) {
            #pragma unroll
            for (int hf = 0; hf < 2; hf++) {
                float bm = -1e30f;
                #pragma unroll
                for (int ni = 0; ni < 8; ni++) {
                    bm = fmaxf(bm, s[mi][ni][hf*2]);
                    bm = fmaxf(bm, s[mi][ni][hf*2+1]);
                }
                bm = fmaxf(bm, __shfl_xor_sync(0xffffffffu, bm, 1));
                bm = fmaxf(bm, __shfl_xor_sync(0xffffffffu, bm, 2));
                float mnew = fmaxf(mrow[mi][hf], bm);
                float corr = __expf(mrow[mi][hf] - mnew);
                mrow[mi][hf] = mnew;
                float rs = 0.f;
                #pragma unroll
                for (int ni = 0; ni < 8; ni++) {
                    float e0 = __expf(s[mi][ni][hf*2]   - mnew);
                    float e1 = __expf(s[mi][ni][hf*2+1] - mnew);
                    s[mi][ni][hf*2]   = e0;
                    s[mi][ni][hf*2+1] = e1;
                    rs += e0 + e1;
                }
                rs += __shfl_xor_sync(0xffffffffu, rs, 1);
                rs += __shfl_xor_sync(0xffffffffu, rs, 2);
                lrow[mi][hf] = lrow[mi][hf] * corr + rs;
                #pragma unroll
                for (int ni = 0; ni < 8; ni++) {
                    o[mi][ni][hf*2]   *= corr;
                    o[mi][ni][hf*2+1] *= corr;
                }
            }
        }

        uint32_t pa[2][4][4];
        #pragma unroll
        for (int mi = 0; mi < 2; mi++)
            #pragma unroll
            for (int st = 0; st < 4; st++) {
                pa[mi][st][0] = packbf(s[mi][2*st][0],   s[mi][2*st][1]);
                pa[mi][st][1] = packbf(s[mi][2*st][2],   s[mi][2*st][3]);
                pa[mi][st][2] = packbf(s[mi][2*st+1][0], s[mi][2*st+1][1]);
                pa[mi][st][3] = packbf(s[mi][2*st+1][2], s[mi][2*st+1][3]);
            }

        #pragma unroll
        for (int st = 0; st < 4; st++) {
            const int vc = blk * 2 + (st >> 1);
            const uint32_t ko = (uint32_t)((st & 1) * 32);
            uint32_t vb[8][2];
            #pragma unroll
            for (int pd = 0; pd < 4; pd++) {
                uint32_t ad = (sb + AV_OFF + vc * 4096 + tile_off(pd * 16 + laneB, cBi)) ^ ko;
                asm volatile(
                    "ldmatrix.sync.aligned.m8n8.x4.shared.b16 {%0,%1,%2,%3}, [%4];"
                    : "=r"(vb[2*pd][0]), "=r"(vb[2*pd][1]), "=r"(vb[2*pd+1][0]), "=r"(vb[2*pd+1][1])
                    : "r"(ad));
            }
            #pragma unroll
            for (int mi = 0; mi < 2; mi++)
                #pragma unroll
                for (int di = 0; di < 8; di++) {
                    asm volatile(
                        "mma.sync.aligned.m16n8k16.row.col.f32.bf16.bf16.f32 "
                        "{%0,%1,%2,%3}, {%4,%5,%6,%7}, {%8,%9}, {%0,%1,%2,%3};"
                        : "+f"(o[mi][di][0]), "+f"(o[mi][di][1]),
                          "+f"(o[mi][di][2]), "+f"(o[mi][di][3])
                        : "r"(pa[mi][st][0]), "r"(pa[mi][st][1]),
                          "r"(pa[mi][st][2]), "r"(pa[mi][st][3]),
                          "r"(vb[di][0]), "r"(vb[di][1]));
                }
        }
    }

    #pragma unroll
    for (int mi = 0; mi < 2; mi++) {
        #pragma unroll
        for (int hf = 0; hf < 2; hf++) {
            int row = tbase + R + mi * 16 + g + hf * 8;
            float inv = 1.0f / lrow[mi][hf];
            #pragma unroll
            for (int ni = 0; ni < 8; ni++) {
                __nv_bfloat162 h2 = __floats2bfloat162_rn(o[mi][ni][hf*2] * inv,
                                                          o[mi][ni][hf*2+1] * inv);
                *(__nv_bfloat162*)(out + (size_t)row * DIM + hoff + ni * 8 + t4 * 2) = h2;
            }
        }
    }
}

// ---------------- biattn pieces ----------------
__global__ void mean_k(const __nv_bfloat16* __restrict__ bx, __nv_bfloat16* __restrict__ xg)
{
    int idx = blockIdx.x * blockDim.x + threadIdx.x;
    if (idx >= BB * NN * DIM) return;
    int d = idx % DIM;
    int n = (idx / DIM) % NN;
    int b = idx / (DIM * NN);
    size_t base = ((size_t)(b * PP) * NN + n) * DIM + d;
    const size_t st = (size_t)NN * DIM;
    float s = __bfloat162float(bx[base]) + __bfloat162float(bx[base + st])
            + __bfloat162float(bx[base + 2*st]) + __bfloat162float(bx[base + 3*st]);
    xg[idx] = __float2bfloat16(0.25f * s);
}

__global__ __launch_bounds__(256)
void sattn_k(const __nv_bfloat16* __restrict__ xl, const __nv_bfloat16* __restrict__ xga,
             const float* __restrict__ ws, const float* __restrict__ bsc,
             float* __restrict__ sa)
{
    int gtid = blockIdx.x * 256 + threadIdx.x;
    int t = gtid >> 5;
    int lane = threadIdx.x & 31;
    if (t >= TT) return;
    int b = t / (PP * NN);
    int n = t % NN;
    const __nv_bfloat16* xlp = xl  + (size_t)t * RED;
    const __nv_bfloat16* xgp = xga + ((size_t)b * NN + n) * RED;
    float s = 0.f;
    for (int i = lane; i < RED; i += 32)
        s += __bfloat162float(xlp[i]) * ws[i] + __bfloat162float(xgp[i]) * ws[RED + i];
    #pragma unroll
    for (int o = 16; o; o >>= 1) s += __shfl_xor_sync(0xffffffffu, s, o);
    if (lane == 0) sa[t] = 1.0f / (1.0f + __expf(-(s + bsc[0])));
}

// ---------------- host driver ----------------
extern "C" void kernel_launch(void* const* d_in, const int* in_sizes, int n_in,
                              void* d_out, int out_size)
{
    const float* x_in  = (const float*)d_in[0];
    const float* ln1_g = (const float*)d_in[1];
    const float* ln1_b = (const float*)d_in[2];
    const float* w_qkv = (const float*)d_in[3];
    const float* w_o   = (const float*)d_in[4];
    const float* b_o   = (const float*)d_in[5];
    const float* ln2_g = (const float*)d_in[6];
    const float* ln2_b = (const float*)d_in[7];
    const float* w1    = (const float*)d_in[8];
    const float* b1    = (const float*)d_in[9];
    const float* w2    = (const float*)d_in[10];
    const float* b2    = (const float*)d_in[11];
    const float* bn_g  = (const float*)d_in[12];
    const float* bn_b  = (const float*)d_in[13];
    const float* wg    = (const float*)d_in[14];
    const float* bg    = (const float*)d_in[15];
    const float* wl    = (const float*)d_in[16];
    const float* bl    = (const float*)d_in[17];
    const float* wc    = (const float*)d_in[18];
    const float* bc    = (const float*)d_in[19];
    const float* ws    = (const float*)d_in[20];
    const float* bs    = (const float*)d_in[21];

    float* base = nullptr;
    cudaGetSymbolAddress((void**)&base, g_scratch);
    float*          X   = base + OFF_X;
    __nv_bfloat16*  Y   = (__nv_bfloat16*)(base + OFF_Y);
    __nv_bfloat16*  QKV = (__nv_bfloat16*)(base + OFF_QKV);
    __nv_bfloat16*  ATT = (__nv_bfloat16*)(base + OFF_ATT);
    __nv_bfloat16*  H1  = (__nv_bfloat16*)(base + OFF_H1);
    float*          H   = base + OFF_H;
    __nv_bfloat16*  BX  = (__nv_bfloat16*)(base + OFF_BX);
    __nv_bfloat16*  XG  = (__nv_bfloat16*)(base + OFF_XG);
    __nv_bfloat16*  XGA = (__nv_bfloat16*)(base + OFF_XGA);
    __nv_bfloat16*  XL  = (__nv_bfloat16*)(base + OFF_XL);
    float*          CA  = base + OFF_CA;
    float*          SA  = base + OFF_SA;
    __nv_bfloat16*  WT  = (__nv_bfloat16*)(base + OFF_WT);

    cudaFuncSetAttribute((const void*)attn2_k,
                         cudaFuncAttributeMaxDynamicSharedMemorySize, ATT2_SMEM);
    cudaFuncSetAttribute((const void*)bgemm_k<EPI_NONE,1,128>,
                         cudaFuncAttributeMaxDynamicSharedMemorySize, GSMEM128);
    cudaFuncSetAttribute((const void*)bgemm_k<EPI_RES,0,128>,
                         cudaFuncAttributeMaxDynamicSharedMemorySize, GSMEM128);
    cudaFuncSetAttribute((const void*)bgemm_k<EPI_GELU,1,128>,
                         cudaFuncAttributeMaxDynamicSharedMemorySize, GSMEM128);
    cudaFuncSetAttribute((const void*)bgemm_k<EPI_BIAS,0,128>,
                         cudaFuncAttributeMaxDynamicSharedMemorySize, GSMEM128);
    cudaFuncSetAttribute((const void*)bgemm_k<EPI_GELU,1,64>,
                         cudaFuncAttributeMaxDynamicSharedMemorySize, GSMEM64);
    cudaFuncSetAttribute((const void*)bgemm_k<EPI_SIG,0,64>,
                         cudaFuncAttributeMaxDynamicSharedMemorySize, GSMEM64);

    const int EW = 256;

    // merged transpose-pack (one launch for all 7 weights)
    packall_k<<<13056, dim3(32, 8)>>>(w_qkv, w_o, w1, w2, wg, wl, wc, WT);

    // layer-0 LN1 straight from input
    ln_k<<<TT, 128>>>(x_in, Y, ln1_g, ln1_b);

    for (int l = 0; l < DEPTH; l++) {
        const float* Xin = (l == 0) ? x_in : X;

        // ---- attention half ----  (Y already holds ln1 output)
        bgemm_k<EPI_NONE,1,128><<<dim3(3*DIM/128, TT/128), 256, GSMEM128>>>(
            Y, WT + WT_QKV + (size_t)l*1536*512, QKV, TT, 3*DIM, DIM, nullptr, nullptr);
        attn2_k<<<BB*PP*HEADS, 256, ATT2_SMEM>>>(QKV, ATT);
        bgemm_k<EPI_RES,0,128><<<dim3(DIM/128, TT/128), 256, GSMEM128>>>(
            ATT, WT + WT_O + (size_t)l*512*512, X, TT, DIM, DIM, b_o + l*DIM, Xin);

        // ---- mlp half ----
        ln_k<<<TT, 128>>>(X, Y, ln2_g + l*DIM, ln2_b + l*DIM);
        bgemm_k<EPI_GELU,1,128><<<dim3(MLPD/128, TT/128), 256, GSMEM128>>>(
            Y, WT + WT_W1 + (size_t)l*2048*512, H1, TT, MLPD, DIM, b1 + l*MLPD, nullptr);
        bgemm_k<EPI_BIAS,0,128><<<dim3(DIM/128, TT/128), 256, GSMEM128>>>(
            H1, WT + WT_W2 + (size_t)l*512*2048, H, TT, DIM, MLPD, b2 + l*DIM, nullptr);

        // ---- biattn ----
        ln_k<<<TT, 128>>>(H, BX, bn_g + l*DIM, bn_b + l*DIM);
        mean_k<<<(BB*NN*DIM + EW - 1) / EW, EW>>>(BX, XG);
        bgemm_k<EPI_GELU,1,64><<<dim3(RED/128, BB*NN/64), 256, GSMEM64>>>(
            XG, WT + WT_WG + (size_t)l*128*512, XGA, BB*NN, RED, DIM, bg + l*RED, nullptr);
        bgemm_k<EPI_GELU,1,64><<<dim3(RED/128, TT/64), 256, GSMEM64>>>(
            BX, WT + WT_WL + (size_t)l*128*512, XL, TT, RED, DIM, bl + l*RED, nullptr);
        bgemm_k<EPI_SIG,0,64><<<dim3(DIM/128, BB*NN/64), 256, GSMEM64>>>(
            XGA, WT + WT_WC + (size_t)l*512*128, CA, BB*NN, DIM, RED, bc + l*DIM, nullptr);
        sattn_k<<<(TT*32 + 255) / 256, 256>>>(XL, XGA, ws + l*2*RED, bs + l, SA);

        // ---- fused residual + next-layer LN1 ----
        if (l < DEPTH - 1) {
            fuseln_k<0><<<TT, 128>>>(H, CA, SA, X, X, Y,
                                     ln1_g + (l+1)*DIM, ln1_b + (l+1)*DIM);
        } else {
            fuseln_k<1><<<TT, 128>>>(H, CA, SA, X, (float*)d_out, nullptr,
                                     nullptr, nullptr);
        }
    }
}